// round 12
// baseline (speedup 1.0000x reference)
#include <cuda_runtime.h>
#include <cuda_fp16.h>
#include <math.h>
#include <stdint.h>

// ---------------- problem constants ----------------
#define Bq   8
#define Nq   1024
#define Dq   1024
#define Hq   16
#define DFFq 4096
#define FACTORq 0.125f
#define QSCALE 0.18033688f   // 0.125 * log2(e)

// ---------------- scratch (device globals) ----------------
__device__ __half g_z[(size_t)Bq * Nq * Dq];
__device__ __half g_qkv[(size_t)Bq * Nq * 3 * Dq];
__device__ float  g_s1[(size_t)Bq * Nq * Dq];
__device__ __half g_h1[(size_t)Bq * Nq * DFFq];
__device__ __half g_whqkv[(size_t)Dq * 3 * Dq];
__device__ __half g_wh1[(size_t)Dq * DFFq];
__device__ __half g_wh2[(size_t)DFFq * Dq];
__device__ __half g_pah[(size_t)Bq * Nq * Nq];   // prior * alpha*F*log2e, half

#define EPI_QKV    0
#define EPI_GELU   1
#define EPI_RES    2

// ---------------- PTX helpers (sm_90+ generic ISA only) ----------------
__device__ __forceinline__ uint32_t smem_u32(const void* p) {
    uint32_t a;
    asm("{ .reg .u64 t; cvta.to.shared.u64 t, %1; cvt.u32.u64 %0, t; }" : "=r"(a) : "l"(p));
    return a;
}
__device__ __forceinline__ void cp16(uint32_t s, const void* g) {
    asm volatile("cp.async.cg.shared.global [%0], [%1], 16;" :: "r"(s), "l"(g));
}
__device__ __forceinline__ void cp_commit() {
    asm volatile("cp.async.commit_group;" ::: "memory");
}
template <int N>
__device__ __forceinline__ void cp_wait() {
    asm volatile("cp.async.wait_group %0;" :: "n"(N) : "memory");
}
__device__ __forceinline__ void gdc_wait() {
    asm volatile("griddepcontrol.wait;" ::: "memory");
}
__device__ __forceinline__ void gdc_launch() {
    asm volatile("griddepcontrol.launch_dependents;");
}
__device__ __forceinline__ void ldm4(uint32_t& r0, uint32_t& r1, uint32_t& r2, uint32_t& r3,
                                     uint32_t addr) {
    asm volatile("ldmatrix.sync.aligned.m8n8.x4.shared.b16 {%0,%1,%2,%3}, [%4];"
                 : "=r"(r0), "=r"(r1), "=r"(r2), "=r"(r3) : "r"(addr));
}
__device__ __forceinline__ void ldm4t(uint32_t& r0, uint32_t& r1, uint32_t& r2, uint32_t& r3,
                                      uint32_t addr) {
    asm volatile("ldmatrix.sync.aligned.m8n8.x4.trans.shared.b16 {%0,%1,%2,%3}, [%4];"
                 : "=r"(r0), "=r"(r1), "=r"(r2), "=r"(r3) : "r"(addr));
}
__device__ __forceinline__ void mma_f16(float* d, const uint32_t* a, const uint32_t* b) {
    asm volatile(
        "mma.sync.aligned.m16n8k16.row.col.f32.f16.f16.f32 "
        "{%0,%1,%2,%3}, {%4,%5,%6,%7}, {%8,%9}, {%0,%1,%2,%3};"
        : "+f"(d[0]), "+f"(d[1]), "+f"(d[2]), "+f"(d[3])
        : "r"(a[0]), "r"(a[1]), "r"(a[2]), "r"(a[3]), "r"(b[0]), "r"(b[1]));
}
// f16-accumulate variant (output packed like next MMA's A fragments).
__device__ __forceinline__ void mma_f16h(uint32_t* d, const uint32_t* a, const uint32_t* b) {
    asm volatile(
        "mma.sync.aligned.m16n8k16.row.col.f16.f16.f16.f16 "
        "{%0,%1}, {%2,%3,%4,%5}, {%6,%7}, {%0,%1};"
        : "+r"(d[0]), "+r"(d[1])
        : "r"(a[0]), "r"(a[1]), "r"(a[2]), "r"(a[3]), "r"(b[0]), "r"(b[1]));
}
__device__ __forceinline__ uint32_t hadd2u(uint32_t a, uint32_t b) {
    uint32_t r;
    asm("add.rn.f16x2 %0, %1, %2;" : "=r"(r) : "r"(a), "r"(b));
    return r;
}
__device__ __forceinline__ uint32_t ex2h2(uint32_t a) {
    uint32_t r;
    asm("ex2.approx.f16x2 %0, %1;" : "=r"(r) : "r"(a));
    return r;
}
__device__ __forceinline__ float tanh_ap(float x) {
    float r;
    asm("tanh.approx.f32 %0, %1;" : "=f"(r) : "f"(x));
    return r;
}
__device__ __forceinline__ uint32_t packh2(float a, float b) {
    __half2 h = __floats2half2_rn(a, b);
    return *(uint32_t*)&h;
}
__device__ __forceinline__ float gelu_fast(float x) {
    float x3 = x * x * x;
    return 0.5f * x * (1.0f + tanh_ap(0.7978845608028654f * (x + 0.044715f * x3)));
}

// ---------------------------------------------------------------------------
// Combined cast: weights fp32->half, prior fp32 -> half*(alpha*F*log2e)
// ---------------------------------------------------------------------------
#define SEG0 786432
#define SEG1 (SEG0 + 1048576)
#define SEG2 (SEG1 + 1048576)
#define SEG3 (SEG2 + 2097152)
__global__ void __launch_bounds__(256)
cast_all_kernel(const float* __restrict__ wqkv, const float* __restrict__ w1,
                const float* __restrict__ w2, const float* __restrict__ prior,
                const float* __restrict__ alpha,
                __half* __restrict__ hq, __half* __restrict__ h1,
                __half* __restrict__ h2, __half* __restrict__ hp)
{
    const int i = blockIdx.x * 256 + threadIdx.x;
    const float* src;
    __half* dst;
    int li;
    float sc = 1.0f;
    if (i < SEG0)      { src = wqkv;  dst = hq; li = i; }
    else if (i < SEG1) { src = w1;    dst = h1; li = i - SEG0; }
    else if (i < SEG2) { src = w2;    dst = h2; li = i - SEG1; }
    else               { src = prior; dst = hp; li = i - SEG2; sc = alpha[0] * QSCALE; }
    float4 v = ((const float4*)src)[li];
    uint2 u;
    u.x = packh2(v.x * sc, v.y * sc);
    u.y = packh2(v.z * sc, v.w * sc);
    ((uint2*)dst)[li] = u;
}

// ---------------------------------------------------------------------------
// LayerNorm, warp-per-row.
// ---------------------------------------------------------------------------
__global__ void __launch_bounds__(256)
ln_kernel(const float* __restrict__ x, const float* __restrict__ g,
          const float* __restrict__ bb, __half* __restrict__ out)
{
    gdc_launch();
    gdc_wait();
    const int warp = threadIdx.x >> 5, lane = threadIdx.x & 31;
    const int row = blockIdx.x * 8 + warp;
    const float4* xr = (const float4*)(x + (size_t)row * Dq);

    float4 v[8];
    float s = 0.0f, s2 = 0.0f;
#pragma unroll
    for (int t = 0; t < 8; t++) {
        v[t] = xr[lane + t * 32];
        s += v[t].x + v[t].y + v[t].z + v[t].w;
        s2 += v[t].x * v[t].x + v[t].y * v[t].y + v[t].z * v[t].z + v[t].w * v[t].w;
    }
#pragma unroll
    for (int o = 16; o; o >>= 1) {
        s += __shfl_xor_sync(0xffffffffu, s, o);
        s2 += __shfl_xor_sync(0xffffffffu, s2, o);
    }
    const float mu = s * (1.0f / Dq);
    const float var = s2 * (1.0f / Dq) - mu * mu;
    const float inv = rsqrtf(var + 1e-5f);

    __half* orow = out + (size_t)row * Dq;
#pragma unroll
    for (int t = 0; t < 8; t++) {
        const int i = (lane + t * 32) * 4;
        float4 gg = *(const float4*)&g[i];
        float4 bv = *(const float4*)&bb[i];
        uint2 u;
        u.x = packh2((v[t].x - mu) * inv * gg.x + bv.x, (v[t].y - mu) * inv * gg.y + bv.y);
        u.y = packh2((v[t].z - mu) * inv * gg.z + bv.z, (v[t].w - mu) * inv * gg.w + bv.w);
        *(uint2*)&orow[i] = u;
    }
}

// ---------------------------------------------------------------------------
// Flash attention v3: 256 q-rows/CTA (32 per warp, mf=2) to halve per-row
// ldmatrix traffic.  half2 softmax; l via ones-MMA; 2 CTAs/SM.
// grid = (N/256, B*H), 256 threads.
// ---------------------------------------------------------------------------
__global__ void __launch_bounds__(256, 2)
flash_kernel(const __half* __restrict__ qkv,
             const __half* __restrict__ pah,
             const float* __restrict__ x,
             float* __restrict__ s1)
{
    constexpr int LDR = 72;
    constexpr int QH = 256 * LDR;        // Q tile halfs
    constexpr int TH = 128 * LDR;        // K/V tile halfs
    extern __shared__ __half sm[];
    const uint32_t ub = smem_u32(sm);

    const int tid = threadIdx.x;
    const int lane = tid & 31;
    const int wid = tid >> 5;
    const int gid = lane >> 2, tig = lane & 3;

    const int qt = blockIdx.x;
    const int bh = blockIdx.y;
    const int b = bh >> 4, h = bh & 15;
    const int q0 = qt * 256;

    const __half* qbase = qkv + (size_t)b * Nq * (3 * Dq) + (size_t)h * 64;
    const __half* kbase = qbase + Dq;
    const __half* vbase = qbase + 2 * Dq;

    gdc_wait();

    auto load_q = [&]() {
#pragma unroll
        for (int t = 0; t < 8; t++) {
            int id = tid + t * 256;
            int r = id >> 3, j = id & 7;
            cp16(ub + (uint32_t)(r * LDR + j * 8) * 2u,
                 qbase + (size_t)(q0 + r) * (3 * Dq) + j * 8);
        }
    };
    auto load_kv = [&](int i) {
        const int kv0 = i * 128;
        const uint32_t sk = ub + (uint32_t)(QH + (i & 1) * 2 * TH) * 2u;
        const uint32_t sv = sk + (uint32_t)TH * 2u;
#pragma unroll
        for (int t = 0; t < 4; t++) {
            int id = tid + t * 256;
            int r = id >> 3, j = id & 7;
            cp16(sk + (uint32_t)(r * LDR + j * 8) * 2u,
                 kbase + (size_t)(kv0 + r) * (3 * Dq) + j * 8);
        }
#pragma unroll
        for (int t = 0; t < 4; t++) {
            int id = tid + t * 256;
            int r = id >> 3, j = id & 7;
            cp16(sv + (uint32_t)(r * LDR + j * 8) * 2u,
                 vbase + (size_t)(kv0 + r) * (3 * Dq) + j * 8);
        }
    };

    load_q();
    load_kv(0);
    cp_commit();

    const uint32_t qa_off = (uint32_t)((wid * 32 + (lane & 15)) * LDR + ((lane >> 4) << 3));
    const uint32_t kb_off = (uint32_t)(((lane & 7) + ((lane >> 4) << 3)) * LDR +
                                       (((lane >> 3) & 1) << 3));
    const uint32_t vb_off = (uint32_t)(((lane & 7) + (((lane >> 3) & 1) << 3)) * LDR +
                                       ((lane >> 4) << 3));

    uint32_t qa[2][4][4];                 // [mf][ks][reg]
    float oacc[2][8][4];                  // [mf][nf][reg]
#pragma unroll
    for (int mf = 0; mf < 2; mf++)
#pragma unroll
        for (int t = 0; t < 8; t++)
#pragma unroll
            for (int q = 0; q < 4; q++) oacc[mf][t][q] = 0.0f;
    float lacc[2][4] = {{0, 0, 0, 0}, {0, 0, 0, 0}};
    const uint32_t ONES = 0x3C003C00u;
    const uint32_t b_ones[2] = {ONES, ONES};

    const __half* prbase = pah + (size_t)b * Nq * Nq +
                           (size_t)(q0 + wid * 32 + gid) * Nq;

    for (int i = 0; i < 8; i++) {
        cp_wait<0>();
        __syncthreads();
        if (i == 0) {
#pragma unroll
            for (int mf = 0; mf < 2; mf++)
#pragma unroll
                for (int ks = 0; ks < 4; ks++)
                    ldm4(qa[mf][ks][0], qa[mf][ks][1], qa[mf][ks][2], qa[mf][ks][3],
                         ub + (qa_off + (uint32_t)(mf * 16 * LDR + ks * 16)) * 2u);
        }
        if (i < 7) {
            load_kv(i + 1);
            cp_commit();
        }

        const uint32_t sk = ub + (uint32_t)(QH + (i & 1) * 2 * TH) * 2u;
        const uint32_t sv = sk + (uint32_t)TH * 2u;

#pragma unroll
        for (int nb = 0; nb < 8; nb++) {
            // ---- S = Q K^T for this 16-col nb block (f16 accum) ----
            uint32_t s2[2][2][2];
#pragma unroll
            for (int mf = 0; mf < 2; mf++) {
                s2[mf][0][0] = 0u; s2[mf][0][1] = 0u;
                s2[mf][1][0] = 0u; s2[mf][1][1] = 0u;
            }
#pragma unroll
            for (int ks = 0; ks < 4; ks++) {
                uint32_t r0, r1, r2, r3;
                ldm4(r0, r1, r2, r3,
                     sk + (kb_off + (uint32_t)(nb * 16 * LDR + ks * 16)) * 2u);
                uint32_t b01[2] = {r0, r1}, b23[2] = {r2, r3};
#pragma unroll
                for (int mf = 0; mf < 2; mf++) {
                    mma_f16h(s2[mf][0], qa[mf][ks], b01);
                    mma_f16h(s2[mf][1], qa[mf][ks], b23);
                }
            }

            // ---- P = 2^(S + pah) ----
            const int kvc = i * 128 + nb * 16 + tig * 2;
#pragma unroll
            for (int mf = 0; mf < 2; mf++) {
                const __half* pr = prbase + (size_t)(mf * 16) * Nq + kvc;
                uint32_t p00 = *(const uint32_t*)pr;
                uint32_t p01 = *(const uint32_t*)(pr + 8 * Nq);
                uint32_t p10 = *(const uint32_t*)(pr + 8);
                uint32_t p11 = *(const uint32_t*)(pr + 8 * Nq + 8);
                s2[mf][0][0] = ex2h2(hadd2u(s2[mf][0][0], p00));
                s2[mf][0][1] = ex2h2(hadd2u(s2[mf][0][1], p01));
                s2[mf][1][0] = ex2h2(hadd2u(s2[mf][1][0], p10));
                s2[mf][1][1] = ex2h2(hadd2u(s2[mf][1][1], p11));
            }

            // ---- l += P @ ones ;  O += P V ----
            uint32_t pa0[4] = {s2[0][0][0], s2[0][0][1], s2[0][1][0], s2[0][1][1]};
            uint32_t pa1[4] = {s2[1][0][0], s2[1][0][1], s2[1][1][0], s2[1][1][1]};
            mma_f16(lacc[0], pa0, b_ones);
            mma_f16(lacc[1], pa1, b_ones);
#pragma unroll
            for (int c = 0; c < 4; c++) {
                uint32_t r0, r1, r2, r3;
                ldm4t(r0, r1, r2, r3,
                      sv + (vb_off + (uint32_t)(nb * 16 * LDR + c * 16)) * 2u);
                uint32_t b01[2] = {r0, r1}, b23[2] = {r2, r3};
                mma_f16(oacc[0][2 * c + 0], pa0, b01);
                mma_f16(oacc[0][2 * c + 1], pa0, b23);
                mma_f16(oacc[1][2 * c + 0], pa1, b01);
                mma_f16(oacc[1][2 * c + 1], pa1, b23);
            }
        }
    }

    gdc_launch();

#pragma unroll
    for (int mf = 0; mf < 2; mf++) {
        const float inv0 = 1.0f / lacc[mf][0], inv1 = 1.0f / lacc[mf][2];
        const int gr0 = q0 + wid * 32 + mf * 16 + gid;
        const size_t o0 = (size_t)b * Nq * Dq + (size_t)gr0 * Dq + h * 64 + tig * 2;
        const size_t o1 = o0 + (size_t)8 * Dq;
#pragma unroll
        for (int t = 0; t < 8; t++) {
            float2 x0 = *(const float2*)(x + o0 + t * 8);
            float2 x1 = *(const float2*)(x + o1 + t * 8);
            float2 w0 = make_float2(oacc[mf][t][0] * inv0 + x0.x,
                                    oacc[mf][t][1] * inv0 + x0.y);
            float2 w1 = make_float2(oacc[mf][t][2] * inv1 + x1.x,
                                    oacc[mf][t][3] * inv1 + x1.y);
            *(float2*)(s1 + o0 + t * 8) = w0;
            *(float2*)(s1 + o1 + t * 8) = w1;
        }
    }
}

// ---------------------------------------------------------------------------
// fp16 mma.sync GEMM (fp32 accum).  BM=128, BN=256, BK=64, 4-stage cp.async.
// A [M,K] half K-major; B [K,N] half row-major (ldmatrix.trans fragments).
// 8 warps 2(M)x4(N); warp tile 64x64.  PDL as before.
// ---------------------------------------------------------------------------
template <int EPI, typename CT>
__global__ void __launch_bounds__(256, 1)
mma_gemm(const __half* __restrict__ A, int lda,
         const __half* __restrict__ B, int ldb,
         CT* __restrict__ C, int ldc, int K,
         const float* __restrict__ e0, const float* __restrict__ e1)
{
    constexpr int BM = 128;
    constexpr int BN = 256;
    constexpr int BK = 64;
    constexpr int S = 4;
    constexpr int LDRA = 72;
    constexpr int LDRB = BN + 8;
    constexpr int AH = BM * LDRA;
    constexpr int BH = BK * LDRB;
    constexpr int STGH = AH + BH;
    constexpr int MF = 4;
    constexpr int NC = 4;

    extern __shared__ __half smh[];
    const uint32_t ubase = smem_u32(smh);

    const int tid = threadIdx.x;
    const int lane = tid & 31;
    const int wid = tid >> 5;
    const int wm = wid >> 2, wn = wid & 3;
    const int gid = lane >> 2, tig = lane & 3;

    const int row0 = blockIdx.y * BM;
    const int col0 = blockIdx.x * BN;
    const int niter = K / BK;

    const uint32_t a_off = (uint32_t)((wm * 64 + (lane & 15)) * LDRA + ((lane >> 4) << 3));
    const uint32_t b_off = (uint32_t)(((lane & 7) + (((lane >> 3) & 1) << 3)) * LDRB +
                                      wn * 64 + ((lane >> 4) << 3));

    auto load_a = [&](int it) {
        const int k0 = it * BK;
        const uint32_t sa = ubase + (uint32_t)((it % S) * STGH) * 2u;
#pragma unroll
        for (int t = 0; t < 4; t++) {
            int id = tid + t * 256;
            int r = id >> 3, j = id & 7;
            cp16(sa + (uint32_t)r * 144u + (uint32_t)j * 16u,
                 A + (size_t)(row0 + r) * lda + k0 + j * 8);
        }
    };
    auto load_b = [&](int it) {
        const int k0 = it * BK;
        const uint32_t sb = ubase + (uint32_t)((it % S) * STGH + AH) * 2u;
#pragma unroll
        for (int t = 0; t < 8; t++) {
            int id = tid + t * 256;
            int r = id >> 5, j = id & 31;
            cp16(sb + (uint32_t)r * (LDRB * 2) + (uint32_t)j * 16u,
                 B + (size_t)(k0 + r) * ldb + col0 + j * 8);
        }
    };

#pragma unroll
    for (int it = 0; it < S - 1; it++) load_b(it);
    gdc_wait();
#pragma unroll
    for (int it = 0; it < S - 1; it++) {
        load_a(it);
        cp_commit();
    }

    float acc[MF][8][4];
#pragma unroll
    for (int mf = 0; mf < MF; mf++)
#pragma unroll
        for (int nf = 0; nf < 8; nf++)
#pragma unroll
            for (int q = 0; q < 4; q++) acc[mf][nf][q] = 0.0f;

    for (int i = 0; i < niter; i++) {
        cp_wait<S - 2>();
        __syncthreads();
        if (i + S - 1 < niter) {
            load_b(i + S - 1);
            load_a(i + S - 1);
        }
        cp_commit();

        const uint32_t sa = ubase + (uint32_t)((i % S) * STGH) * 2u;
        const uint32_t sb = ubase + (uint32_t)((i % S) * STGH + AH) * 2u;

#pragma unroll
        for (int ks = 0; ks < BK / 16; ks++) {
            uint32_t a[MF][4], b[NC][4];
#pragma unroll
            for (int mf = 0; mf < MF; mf++)
                ldm4(a[mf][0], a[mf][1], a[mf][2], a[mf][3],
                     sa + (a_off + (uint32_t)(mf * 16 * LDRA + ks * 16)) * 2u);
#pragma unroll
            for (int c = 0; c < NC; c++)
                ldm4t(b[c][0], b[c][1], b[c][2], b[c][3],
                      sb + (b_off + (uint32_t)(ks * 16 * LDRB + c * 16)) * 2u);
#pragma unroll
            for (int mf = 0; mf < MF; mf++)
#pragma unroll
                for (int c = 0; c < NC; c++) {
                    mma_f16(acc[mf][2 * c + 0], a[mf], &b[c][0]);
                    mma_f16(acc[mf][2 * c + 1], a[mf], &b[c][2]);
                }
        }
    }

    gdc_launch();

#pragma unroll
    for (int mf = 0; mf < MF; mf++) {
        const int gr0 = row0 + wm * 64 + mf * 16 + gid;
#pragma unroll
        for (int nf = 0; nf < 8; nf++) {
            const int gc = col0 + wn * 64 + nf * 8 + tig * 2;
#pragma unroll
            for (int half_ = 0; half_ < 2; half_++) {
                const int gr = gr0 + half_ * 8;
                float v0 = acc[mf][nf][half_ * 2 + 0];
                float v1 = acc[mf][nf][half_ * 2 + 1];
                float o0, o1;
                if constexpr (EPI == EPI_QKV) {
                    o0 = v0 + e0[gc]; o1 = v1 + e0[gc + 1];
                    if (gc < Dq) { o0 *= QSCALE; o1 *= QSCALE; }
                } else if constexpr (EPI == EPI_GELU) {
                    o0 = gelu_fast(v0 + e0[gc]); o1 = gelu_fast(v1 + e0[gc + 1]);
                } else {  // EPI_RES
                    float2 rr = *(const float2*)&e1[(size_t)gr * ldc + gc];
                    o0 = v0 + e0[gc] + rr.x; o1 = v1 + e0[gc + 1] + rr.y;
                }
                if constexpr (sizeof(CT) == 2) {
                    *(__half2*)&C[(size_t)gr * ldc + gc] = __floats2half2_rn(o0, o1);
                } else {
                    *(float2*)&C[(size_t)gr * ldc + gc] = make_float2(o0, o1);
                }
            }
        }
    }
}

// ---------------------------------------------------------------------------
// launch
// ---------------------------------------------------------------------------
extern "C" void kernel_launch(void* const* d_in, const int* in_sizes, int n_in,
                              void* d_out, int out_size)
{
    const float* x     = (const float*)d_in[0];
    const float* prior = (const float*)d_in[1];
    const float* Wqkv  = (const float*)d_in[2];
    const float* bqkv  = (const float*)d_in[3];
    const float* alpha = (const float*)d_in[4];
    const float* ln1_g = (const float*)d_in[5];
    const float* ln1_b = (const float*)d_in[6];
    const float* ln2_g = (const float*)d_in[7];
    const float* ln2_b = (const float*)d_in[8];
    const float* w1    = (const float*)d_in[9];
    const float* b1    = (const float*)d_in[10];
    const float* w2    = (const float*)d_in[11];
    const float* b2    = (const float*)d_in[12];
    float* out = (float*)d_out;

    __half *zp, *qkvp, *h1p, *whqkv, *wh1, *wh2, *pahp;
    float* s1p;
    cudaGetSymbolAddress((void**)&zp, g_z);
    cudaGetSymbolAddress((void**)&qkvp, g_qkv);
    cudaGetSymbolAddress((void**)&s1p, g_s1);
    cudaGetSymbolAddress((void**)&h1p, g_h1);
    cudaGetSymbolAddress((void**)&whqkv, g_whqkv);
    cudaGetSymbolAddress((void**)&wh1, g_wh1);
    cudaGetSymbolAddress((void**)&wh2, g_wh2);
    cudaGetSymbolAddress((void**)&pahp, g_pah);

    const int smem_g  = 4 * (128 * 72 + 64 * 264) * 2;   // 208896
    const int smem_fa = (256 * 72 + 4 * 128 * 72) * 2;   // 110592
    cudaFuncSetAttribute(mma_gemm<EPI_QKV, __half>,  cudaFuncAttributeMaxDynamicSharedMemorySize, smem_g);
    cudaFuncSetAttribute(mma_gemm<EPI_GELU, __half>, cudaFuncAttributeMaxDynamicSharedMemorySize, smem_g);
    cudaFuncSetAttribute(mma_gemm<EPI_RES, float>,   cudaFuncAttributeMaxDynamicSharedMemorySize, smem_g);
    cudaFuncSetAttribute(flash_kernel, cudaFuncAttributeMaxDynamicSharedMemorySize, smem_fa);

    const int rows = Bq * Nq;  // 8192

    cudaLaunchAttribute pattr[1];
    pattr[0].id = cudaLaunchAttributeProgrammaticStreamSerialization;
    pattr[0].val.programmaticStreamSerializationAllowed = 1;

    // 0) all casts in one kernel
    cast_all_kernel<<<SEG3 / 256, 256>>>(Wqkv, w1, w2, prior, alpha,
                                         whqkv, wh1, wh2, pahp);

    // 1) z = LN1(x)
    {
        cudaLaunchConfig_t cfg{};
        cfg.gridDim = dim3(rows / 8); cfg.blockDim = dim3(256);
        cfg.attrs = pattr; cfg.numAttrs = 1;
        cudaLaunchKernelEx(&cfg, ln_kernel, x, ln1_g, ln1_b, (__half*)zp);
    }
    // 2) qkv = z @ Wqkv + bqkv
    {
        cudaLaunchConfig_t cfg{};
        cfg.gridDim = dim3(3 * Dq / 256, rows / 128); cfg.blockDim = dim3(256);
        cfg.dynamicSmemBytes = smem_g; cfg.attrs = pattr; cfg.numAttrs = 1;
        cudaLaunchKernelEx(&cfg, mma_gemm<EPI_QKV, __half>,
                           (const __half*)zp, (int)Dq, (const __half*)whqkv, (int)(3 * Dq),
                           (__half*)qkvp, (int)(3 * Dq), (int)Dq, bqkv, (const float*)nullptr);
    }
    // 3) fused attention (256-row q tiles)
    {
        cudaLaunchConfig_t cfg{};
        cfg.gridDim = dim3(Nq / 256, Bq * Hq); cfg.blockDim = dim3(256);
        cfg.dynamicSmemBytes = smem_fa; cfg.attrs = pattr; cfg.numAttrs = 1;
        cudaLaunchKernelEx(&cfg, flash_kernel,
                           (const __half*)qkvp, (const __half*)pahp, x, (float*)s1p);
    }
    // 4) z = LN2(s1)
    {
        cudaLaunchConfig_t cfg{};
        cfg.gridDim = dim3(rows / 8); cfg.blockDim = dim3(256);
        cfg.attrs = pattr; cfg.numAttrs = 1;
        cudaLaunchKernelEx(&cfg, ln_kernel, (const float*)s1p, ln2_g, ln2_b, (__half*)zp);
    }
    // 5) h1 = gelu(z @ w1 + b1)
    {
        cudaLaunchConfig_t cfg{};
        cfg.gridDim = dim3(DFFq / 256, rows / 128); cfg.blockDim = dim3(256);
        cfg.dynamicSmemBytes = smem_g; cfg.attrs = pattr; cfg.numAttrs = 1;
        cudaLaunchKernelEx(&cfg, mma_gemm<EPI_GELU, __half>,
                           (const __half*)zp, (int)Dq, (const __half*)wh1, (int)DFFq,
                           (__half*)h1p, (int)DFFq, (int)Dq, b1, (const float*)nullptr);
    }
    // 6) out = s1 + h1 @ w2 + b2
    {
        cudaLaunchConfig_t cfg{};
        cfg.gridDim = dim3(Dq / 256, rows / 128); cfg.blockDim = dim3(256);
        cfg.dynamicSmemBytes = smem_g; cfg.attrs = pattr; cfg.numAttrs = 1;
        cudaLaunchKernelEx(&cfg, mma_gemm<EPI_RES, float>,
                           (const __half*)h1p, (int)DFFq, (const __half*)wh2, (int)Dq,
                           out, (int)Dq, (int)DFFq, b2, (const float*)s1p);
    }
}

// round 13
// speedup vs baseline: 1.0285x; 1.0285x over previous
#include <cuda_runtime.h>
#include <cuda_fp16.h>
#include <math.h>
#include <stdint.h>

// ---------------- problem constants ----------------
#define Bq   8
#define Nq   1024
#define Dq   1024
#define Hq   16
#define DFFq 4096
#define FACTORq 0.125f
#define QSCALE 0.18033688f   // 0.125 * log2(e)

// ---------------- scratch (device globals) ----------------
__device__ __half g_z[(size_t)Bq * Nq * Dq];
__device__ __half g_qkv[(size_t)Bq * Nq * 3 * Dq];
__device__ float  g_s1[(size_t)Bq * Nq * Dq];
__device__ __half g_h1[(size_t)Bq * Nq * DFFq];
__device__ __half g_whqkv[(size_t)Dq * 3 * Dq];
__device__ __half g_wh1[(size_t)Dq * DFFq];
__device__ __half g_wh2[(size_t)DFFq * Dq];
__device__ __half g_pah[(size_t)Bq * Nq * Nq];   // prior * alpha*F*log2e, half

#define EPI_QKV    0
#define EPI_GELU   1
#define EPI_RES    2

// ---------------- PTX helpers (sm_90+ generic ISA only) ----------------
__device__ __forceinline__ uint32_t smem_u32(const void* p) {
    uint32_t a;
    asm("{ .reg .u64 t; cvta.to.shared.u64 t, %1; cvt.u32.u64 %0, t; }" : "=r"(a) : "l"(p));
    return a;
}
__device__ __forceinline__ void cp16(uint32_t s, const void* g) {
    asm volatile("cp.async.cg.shared.global [%0], [%1], 16;" :: "r"(s), "l"(g));
}
__device__ __forceinline__ void cp_commit() {
    asm volatile("cp.async.commit_group;" ::: "memory");
}
template <int N>
__device__ __forceinline__ void cp_wait() {
    asm volatile("cp.async.wait_group %0;" :: "n"(N) : "memory");
}
__device__ __forceinline__ void gdc_wait() {
    asm volatile("griddepcontrol.wait;" ::: "memory");
}
__device__ __forceinline__ void gdc_launch() {
    asm volatile("griddepcontrol.launch_dependents;");
}
__device__ __forceinline__ void ldm4(uint32_t& r0, uint32_t& r1, uint32_t& r2, uint32_t& r3,
                                     uint32_t addr) {
    asm volatile("ldmatrix.sync.aligned.m8n8.x4.shared.b16 {%0,%1,%2,%3}, [%4];"
                 : "=r"(r0), "=r"(r1), "=r"(r2), "=r"(r3) : "r"(addr));
}
__device__ __forceinline__ void ldm4t(uint32_t& r0, uint32_t& r1, uint32_t& r2, uint32_t& r3,
                                      uint32_t addr) {
    asm volatile("ldmatrix.sync.aligned.m8n8.x4.trans.shared.b16 {%0,%1,%2,%3}, [%4];"
                 : "=r"(r0), "=r"(r1), "=r"(r2), "=r"(r3) : "r"(addr));
}
__device__ __forceinline__ void mma_f16(float* d, const uint32_t* a, const uint32_t* b) {
    asm volatile(
        "mma.sync.aligned.m16n8k16.row.col.f32.f16.f16.f32 "
        "{%0,%1,%2,%3}, {%4,%5,%6,%7}, {%8,%9}, {%0,%1,%2,%3};"
        : "+f"(d[0]), "+f"(d[1]), "+f"(d[2]), "+f"(d[3])
        : "r"(a[0]), "r"(a[1]), "r"(a[2]), "r"(a[3]), "r"(b[0]), "r"(b[1]));
}
// f16-accumulate variant (output packed like next MMA's A fragments).
__device__ __forceinline__ void mma_f16h(uint32_t* d, const uint32_t* a, const uint32_t* b) {
    asm volatile(
        "mma.sync.aligned.m16n8k16.row.col.f16.f16.f16.f16 "
        "{%0,%1}, {%2,%3,%4,%5}, {%6,%7}, {%0,%1};"
        : "+r"(d[0]), "+r"(d[1])
        : "r"(a[0]), "r"(a[1]), "r"(a[2]), "r"(a[3]), "r"(b[0]), "r"(b[1]));
}
__device__ __forceinline__ uint32_t hadd2u(uint32_t a, uint32_t b) {
    uint32_t r;
    asm("add.rn.f16x2 %0, %1, %2;" : "=r"(r) : "r"(a), "r"(b));
    return r;
}
__device__ __forceinline__ uint32_t ex2h2(uint32_t a) {
    uint32_t r;
    asm("ex2.approx.f16x2 %0, %1;" : "=r"(r) : "r"(a));
    return r;
}
__device__ __forceinline__ float tanh_ap(float x) {
    float r;
    asm("tanh.approx.f32 %0, %1;" : "=f"(r) : "f"(x));
    return r;
}
__device__ __forceinline__ uint32_t packh2(float a, float b) {
    __half2 h = __floats2half2_rn(a, b);
    return *(uint32_t*)&h;
}
__device__ __forceinline__ float gelu_fast(float x) {
    float x3 = x * x * x;
    return 0.5f * x * (1.0f + tanh_ap(0.7978845608028654f * (x + 0.044715f * x3)));
}

// ---------------------------------------------------------------------------
// Prep kernel: weights fp32->half, prior fp32 -> half*(alpha*F*log2e),
// AND LN1(x) -> z  (LN runs concurrently with the casts instead of after).
// ---------------------------------------------------------------------------
#define SEG0 786432               // Wqkv:  1024*3072/4 float4
#define SEG1 (SEG0 + 1048576)     // w1
#define SEG2 (SEG1 + 1048576)     // w2
#define SEG3 (SEG2 + 2097152)     // prior
#define CAST_BLOCKS (SEG3 / 256)  // 19456
#define LN_BLOCKS (Bq * Nq / 8)   // 1024
__global__ void __launch_bounds__(256)
prep_kernel(const float* __restrict__ wqkv, const float* __restrict__ w1,
            const float* __restrict__ w2, const float* __restrict__ prior,
            const float* __restrict__ alpha,
            const float* __restrict__ x, const float* __restrict__ ln_g,
            const float* __restrict__ ln_b,
            __half* __restrict__ hq, __half* __restrict__ h1,
            __half* __restrict__ h2, __half* __restrict__ hp,
            __half* __restrict__ z)
{
    if (blockIdx.x < CAST_BLOCKS) {
        const int i = blockIdx.x * 256 + threadIdx.x;
        const float* src;
        __half* dst;
        int li;
        float sc = 1.0f;
        if (i < SEG0)      { src = wqkv;  dst = hq; li = i; }
        else if (i < SEG1) { src = w1;    dst = h1; li = i - SEG0; }
        else if (i < SEG2) { src = w2;    dst = h2; li = i - SEG1; }
        else               { src = prior; dst = hp; li = i - SEG2; sc = alpha[0] * QSCALE; }
        float4 v = ((const float4*)src)[li];
        uint2 u;
        u.x = packh2(v.x * sc, v.y * sc);
        u.y = packh2(v.z * sc, v.w * sc);
        ((uint2*)dst)[li] = u;
        return;
    }
    // ---- LN1 segment: warp-per-row ----
    const int warp = threadIdx.x >> 5, lane = threadIdx.x & 31;
    const int row = (blockIdx.x - CAST_BLOCKS) * 8 + warp;
    const float4* xr = (const float4*)(x + (size_t)row * Dq);

    float4 v[8];
    float s = 0.0f, s2 = 0.0f;
#pragma unroll
    for (int t = 0; t < 8; t++) {
        v[t] = xr[lane + t * 32];
        s += v[t].x + v[t].y + v[t].z + v[t].w;
        s2 += v[t].x * v[t].x + v[t].y * v[t].y + v[t].z * v[t].z + v[t].w * v[t].w;
    }
#pragma unroll
    for (int o = 16; o; o >>= 1) {
        s += __shfl_xor_sync(0xffffffffu, s, o);
        s2 += __shfl_xor_sync(0xffffffffu, s2, o);
    }
    const float mu = s * (1.0f / Dq);
    const float var = s2 * (1.0f / Dq) - mu * mu;
    const float inv = rsqrtf(var + 1e-5f);

    __half* orow = z + (size_t)row * Dq;
#pragma unroll
    for (int t = 0; t < 8; t++) {
        const int i = (lane + t * 32) * 4;
        float4 gg = *(const float4*)&ln_g[i];
        float4 bv = *(const float4*)&ln_b[i];
        uint2 u;
        u.x = packh2((v[t].x - mu) * inv * gg.x + bv.x, (v[t].y - mu) * inv * gg.y + bv.y);
        u.y = packh2((v[t].z - mu) * inv * gg.z + bv.z, (v[t].w - mu) * inv * gg.w + bv.w);
        *(uint2*)&orow[i] = u;
    }
}

// ---------------------------------------------------------------------------
// LayerNorm, warp-per-row (used for LN2 only).
// ---------------------------------------------------------------------------
__global__ void __launch_bounds__(256)
ln_kernel(const float* __restrict__ x, const float* __restrict__ g,
          const float* __restrict__ bb, __half* __restrict__ out)
{
    gdc_launch();
    gdc_wait();
    const int warp = threadIdx.x >> 5, lane = threadIdx.x & 31;
    const int row = blockIdx.x * 8 + warp;
    const float4* xr = (const float4*)(x + (size_t)row * Dq);

    float4 v[8];
    float s = 0.0f, s2 = 0.0f;
#pragma unroll
    for (int t = 0; t < 8; t++) {
        v[t] = xr[lane + t * 32];
        s += v[t].x + v[t].y + v[t].z + v[t].w;
        s2 += v[t].x * v[t].x + v[t].y * v[t].y + v[t].z * v[t].z + v[t].w * v[t].w;
    }
#pragma unroll
    for (int o = 16; o; o >>= 1) {
        s += __shfl_xor_sync(0xffffffffu, s, o);
        s2 += __shfl_xor_sync(0xffffffffu, s2, o);
    }
    const float mu = s * (1.0f / Dq);
    const float var = s2 * (1.0f / Dq) - mu * mu;
    const float inv = rsqrtf(var + 1e-5f);

    __half* orow = out + (size_t)row * Dq;
#pragma unroll
    for (int t = 0; t < 8; t++) {
        const int i = (lane + t * 32) * 4;
        float4 gg = *(const float4*)&g[i];
        float4 bv = *(const float4*)&bb[i];
        uint2 u;
        u.x = packh2((v[t].x - mu) * inv * gg.x + bv.x, (v[t].y - mu) * inv * gg.y + bv.y);
        u.y = packh2((v[t].z - mu) * inv * gg.z + bv.z, (v[t].w - mu) * inv * gg.w + bv.w);
        *(uint2*)&orow[i] = u;
    }
}

// ---------------------------------------------------------------------------
// Flash attention (exact R11 config): half2-domain softmax, 2 CTAs/SM,
// kv tile processed in two nb-halves; 128 q-rows/CTA, 16 per warp.
// grid = (N/128, B*H), 256 threads.
// ---------------------------------------------------------------------------
__global__ void __launch_bounds__(256, 2)
flash_kernel(const __half* __restrict__ qkv,
             const __half* __restrict__ pah,
             const float* __restrict__ x,
             float* __restrict__ s1)
{
    constexpr int LDR = 72;
    constexpr int TH = 128 * LDR;
    extern __shared__ __half sm[];
    const uint32_t ub = smem_u32(sm);

    const int tid = threadIdx.x;
    const int lane = tid & 31;
    const int wid = tid >> 5;
    const int gid = lane >> 2, tig = lane & 3;

    const int qt = blockIdx.x;
    const int bh = blockIdx.y;
    const int b = bh >> 4, h = bh & 15;
    const int q0 = qt * 128;

    const __half* qbase = qkv + (size_t)b * Nq * (3 * Dq) + (size_t)h * 64;
    const __half* kbase = qbase + Dq;
    const __half* vbase = qbase + 2 * Dq;

    gdc_wait();

    auto load_q = [&]() {
#pragma unroll
        for (int t = 0; t < 4; t++) {
            int id = tid + t * 256;
            int r = id >> 3, j = id & 7;
            cp16(ub + (uint32_t)(r * LDR + j * 8) * 2u,
                 qbase + (size_t)(q0 + r) * (3 * Dq) + j * 8);
        }
    };
    auto load_kv = [&](int i) {
        const int kv0 = i * 128;
        const uint32_t sk = ub + (uint32_t)(TH * (1 + 2 * (i & 1))) * 2u;
        const uint32_t sv = sk + (uint32_t)TH * 2u;
#pragma unroll
        for (int t = 0; t < 4; t++) {
            int id = tid + t * 256;
            int r = id >> 3, j = id & 7;
            cp16(sk + (uint32_t)(r * LDR + j * 8) * 2u,
                 kbase + (size_t)(kv0 + r) * (3 * Dq) + j * 8);
        }
#pragma unroll
        for (int t = 0; t < 4; t++) {
            int id = tid + t * 256;
            int r = id >> 3, j = id & 7;
            cp16(sv + (uint32_t)(r * LDR + j * 8) * 2u,
                 vbase + (size_t)(kv0 + r) * (3 * Dq) + j * 8);
        }
    };

    load_q();
    load_kv(0);
    cp_commit();

    const uint32_t qa_off = (uint32_t)((wid * 16 + (lane & 15)) * LDR + ((lane >> 4) << 3));
    const uint32_t kb_off = (uint32_t)(((lane & 7) + ((lane >> 4) << 3)) * LDR +
                                       (((lane >> 3) & 1) << 3));
    const uint32_t vb_off = (uint32_t)(((lane & 7) + (((lane >> 3) & 1) << 3)) * LDR +
                                       ((lane >> 4) << 3));

    uint32_t qa[4][4];
    float oacc[8][4];
#pragma unroll
    for (int t = 0; t < 8; t++)
#pragma unroll
        for (int q = 0; q < 4; q++) oacc[t][q] = 0.0f;
    float lacc[4] = {0.0f, 0.0f, 0.0f, 0.0f};
    const uint32_t ONES = 0x3C003C00u;
    const uint32_t b_ones[2] = {ONES, ONES};

    const __half* prh0 = pah + (size_t)b * Nq * Nq + (size_t)(q0 + wid * 16 + gid) * Nq;
    const __half* prh1 = prh0 + 8 * Nq;

    for (int i = 0; i < 8; i++) {
        cp_wait<0>();
        __syncthreads();
        if (i == 0) {
#pragma unroll
            for (int ks = 0; ks < 4; ks++)
                ldm4(qa[ks][0], qa[ks][1], qa[ks][2], qa[ks][3],
                     ub + (qa_off + (uint32_t)(ks * 16)) * 2u);
        }
        if (i < 7) {
            load_kv(i + 1);
            cp_commit();
        }

        const uint32_t sk = ub + (uint32_t)(TH * (1 + 2 * (i & 1))) * 2u;
        const uint32_t sv = sk + (uint32_t)TH * 2u;

        // process kv tile in two halves of 64 columns (4 nb blocks each)
#pragma unroll
        for (int h2 = 0; h2 < 2; h2++) {
            uint32_t s2[8][2];
#pragma unroll
            for (int j = 0; j < 8; j++) { s2[j][0] = 0u; s2[j][1] = 0u; }
#pragma unroll
            for (int ks = 0; ks < 4; ks++) {
#pragma unroll
                for (int nb = 0; nb < 4; nb++) {
                    uint32_t r0, r1, r2, r3;
                    ldm4(r0, r1, r2, r3,
                         sk + (kb_off + (uint32_t)(((h2 * 4 + nb) * 16) * LDR + ks * 16)) * 2u);
                    uint32_t b01[2] = {r0, r1}, b23[2] = {r2, r3};
                    mma_f16h(s2[2 * nb + 0], qa[ks], b01);
                    mma_f16h(s2[2 * nb + 1], qa[ks], b23);
                }
            }

            const int kvc = i * 128 + h2 * 64 + tig * 2;
#pragma unroll
            for (int j = 0; j < 8; j++) {
                uint32_t pp0 = *(const uint32_t*)(prh0 + kvc + j * 8);
                uint32_t pp1 = *(const uint32_t*)(prh1 + kvc + j * 8);
                s2[j][0] = ex2h2(hadd2u(s2[j][0], pp0));
                s2[j][1] = ex2h2(hadd2u(s2[j][1], pp1));
            }

#pragma unroll
            for (int ks = 0; ks < 4; ks++) {
                uint32_t pa[4] = {s2[2 * ks][0], s2[2 * ks][1],
                                  s2[2 * ks + 1][0], s2[2 * ks + 1][1]};
                mma_f16(lacc, pa, b_ones);
#pragma unroll
                for (int c = 0; c < 4; c++) {
                    uint32_t r0, r1, r2, r3;
                    ldm4t(r0, r1, r2, r3,
                          sv + (vb_off + (uint32_t)(((h2 * 4 + ks) * 16) * LDR + c * 16)) * 2u);
                    uint32_t b01[2] = {r0, r1}, b23[2] = {r2, r3};
                    mma_f16(oacc[2 * c + 0], pa, b01);
                    mma_f16(oacc[2 * c + 1], pa, b23);
                }
            }
        }
    }

    gdc_launch();

    const float inv0 = 1.0f / lacc[0], inv1 = 1.0f / lacc[2];

    const int gr0 = q0 + wid * 16 + gid;
    const size_t o0 = (size_t)b * Nq * Dq + (size_t)gr0 * Dq + h * 64 + tig * 2;
    const size_t o1 = o0 + (size_t)8 * Dq;
#pragma unroll
    for (int t = 0; t < 8; t++) {
        float2 x0 = *(const float2*)(x + o0 + t * 8);
        float2 x1 = *(const float2*)(x + o1 + t * 8);
        float2 w0 = make_float2(oacc[t][0] * inv0 + x0.x, oacc[t][1] * inv0 + x0.y);
        float2 w1 = make_float2(oacc[t][2] * inv1 + x1.x, oacc[t][3] * inv1 + x1.y);
        *(float2*)(s1 + o0 + t * 8) = w0;
        *(float2*)(s1 + o1 + t * 8) = w1;
    }
}

// ---------------------------------------------------------------------------
// fp16 mma.sync GEMM (fp32 accum).  BM=128, BN=256, BK=64, 4-stage cp.async.
// A [M,K] half K-major; B [K,N] half row-major (ldmatrix.trans fragments).
// 8 warps 2(M)x4(N); warp tile 64x64.  PDL as before.
// ---------------------------------------------------------------------------
template <int EPI, typename CT>
__global__ void __launch_bounds__(256, 1)
mma_gemm(const __half* __restrict__ A, int lda,
         const __half* __restrict__ B, int ldb,
         CT* __restrict__ C, int ldc, int K,
         const float* __restrict__ e0, const float* __restrict__ e1)
{
    constexpr int BM = 128;
    constexpr int BN = 256;
    constexpr int BK = 64;
    constexpr int S = 4;
    constexpr int LDRA = 72;
    constexpr int LDRB = BN + 8;
    constexpr int AH = BM * LDRA;
    constexpr int BH = BK * LDRB;
    constexpr int STGH = AH + BH;
    constexpr int MF = 4;
    constexpr int NC = 4;

    extern __shared__ __half smh[];
    const uint32_t ubase = smem_u32(smh);

    const int tid = threadIdx.x;
    const int lane = tid & 31;
    const int wid = tid >> 5;
    const int wm = wid >> 2, wn = wid & 3;
    const int gid = lane >> 2, tig = lane & 3;

    const int row0 = blockIdx.y * BM;
    const int col0 = blockIdx.x * BN;
    const int niter = K / BK;

    const uint32_t a_off = (uint32_t)((wm * 64 + (lane & 15)) * LDRA + ((lane >> 4) << 3));
    const uint32_t b_off = (uint32_t)(((lane & 7) + (((lane >> 3) & 1) << 3)) * LDRB +
                                      wn * 64 + ((lane >> 4) << 3));

    auto load_a = [&](int it) {
        const int k0 = it * BK;
        const uint32_t sa = ubase + (uint32_t)((it % S) * STGH) * 2u;
#pragma unroll
        for (int t = 0; t < 4; t++) {
            int id = tid + t * 256;
            int r = id >> 3, j = id & 7;
            cp16(sa + (uint32_t)r * 144u + (uint32_t)j * 16u,
                 A + (size_t)(row0 + r) * lda + k0 + j * 8);
        }
    };
    auto load_b = [&](int it) {
        const int k0 = it * BK;
        const uint32_t sb = ubase + (uint32_t)((it % S) * STGH + AH) * 2u;
#pragma unroll
        for (int t = 0; t < 8; t++) {
            int id = tid + t * 256;
            int r = id >> 5, j = id & 31;
            cp16(sb + (uint32_t)r * (LDRB * 2) + (uint32_t)j * 16u,
                 B + (size_t)(k0 + r) * ldb + col0 + j * 8);
        }
    };

#pragma unroll
    for (int it = 0; it < S - 1; it++) load_b(it);
    gdc_wait();
#pragma unroll
    for (int it = 0; it < S - 1; it++) {
        load_a(it);
        cp_commit();
    }

    float acc[MF][8][4];
#pragma unroll
    for (int mf = 0; mf < MF; mf++)
#pragma unroll
        for (int nf = 0; nf < 8; nf++)
#pragma unroll
            for (int q = 0; q < 4; q++) acc[mf][nf][q] = 0.0f;

    for (int i = 0; i < niter; i++) {
        cp_wait<S - 2>();
        __syncthreads();
        if (i + S - 1 < niter) {
            load_b(i + S - 1);
            load_a(i + S - 1);
        }
        cp_commit();

        const uint32_t sa = ubase + (uint32_t)((i % S) * STGH) * 2u;
        const uint32_t sb = ubase + (uint32_t)((i % S) * STGH + AH) * 2u;

#pragma unroll
        for (int ks = 0; ks < BK / 16; ks++) {
            uint32_t a[MF][4], b[NC][4];
#pragma unroll
            for (int mf = 0; mf < MF; mf++)
                ldm4(a[mf][0], a[mf][1], a[mf][2], a[mf][3],
                     sa + (a_off + (uint32_t)(mf * 16 * LDRA + ks * 16)) * 2u);
#pragma unroll
            for (int c = 0; c < NC; c++)
                ldm4t(b[c][0], b[c][1], b[c][2], b[c][3],
                      sb + (b_off + (uint32_t)(ks * 16 * LDRB + c * 16)) * 2u);
#pragma unroll
            for (int mf = 0; mf < MF; mf++)
#pragma unroll
                for (int c = 0; c < NC; c++) {
                    mma_f16(acc[mf][2 * c + 0], a[mf], &b[c][0]);
                    mma_f16(acc[mf][2 * c + 1], a[mf], &b[c][2]);
                }
        }
    }

    gdc_launch();

#pragma unroll
    for (int mf = 0; mf < MF; mf++) {
        const int gr0 = row0 + wm * 64 + mf * 16 + gid;
#pragma unroll
        for (int nf = 0; nf < 8; nf++) {
            const int gc = col0 + wn * 64 + nf * 8 + tig * 2;
#pragma unroll
            for (int half_ = 0; half_ < 2; half_++) {
                const int gr = gr0 + half_ * 8;
                float v0 = acc[mf][nf][half_ * 2 + 0];
                float v1 = acc[mf][nf][half_ * 2 + 1];
                float o0, o1;
                if constexpr (EPI == EPI_QKV) {
                    o0 = v0 + e0[gc]; o1 = v1 + e0[gc + 1];
                    if (gc < Dq) { o0 *= QSCALE; o1 *= QSCALE; }
                } else if constexpr (EPI == EPI_GELU) {
                    o0 = gelu_fast(v0 + e0[gc]); o1 = gelu_fast(v1 + e0[gc + 1]);
                } else {  // EPI_RES
                    float2 rr = *(const float2*)&e1[(size_t)gr * ldc + gc];
                    o0 = v0 + e0[gc] + rr.x; o1 = v1 + e0[gc + 1] + rr.y;
                }
                if constexpr (sizeof(CT) == 2) {
                    *(__half2*)&C[(size_t)gr * ldc + gc] = __floats2half2_rn(o0, o1);
                } else {
                    *(float2*)&C[(size_t)gr * ldc + gc] = make_float2(o0, o1);
                }
            }
        }
    }
}

// ---------------------------------------------------------------------------
// launch
// ---------------------------------------------------------------------------
extern "C" void kernel_launch(void* const* d_in, const int* in_sizes, int n_in,
                              void* d_out, int out_size)
{
    const float* x     = (const float*)d_in[0];
    const float* prior = (const float*)d_in[1];
    const float* Wqkv  = (const float*)d_in[2];
    const float* bqkv  = (const float*)d_in[3];
    const float* alpha = (const float*)d_in[4];
    const float* ln1_g = (const float*)d_in[5];
    const float* ln1_b = (const float*)d_in[6];
    const float* ln2_g = (const float*)d_in[7];
    const float* ln2_b = (const float*)d_in[8];
    const float* w1    = (const float*)d_in[9];
    const float* b1    = (const float*)d_in[10];
    const float* w2    = (const float*)d_in[11];
    const float* b2    = (const float*)d_in[12];
    float* out = (float*)d_out;

    __half *zp, *qkvp, *h1p, *whqkv, *wh1, *wh2, *pahp;
    float* s1p;
    cudaGetSymbolAddress((void**)&zp, g_z);
    cudaGetSymbolAddress((void**)&qkvp, g_qkv);
    cudaGetSymbolAddress((void**)&s1p, g_s1);
    cudaGetSymbolAddress((void**)&h1p, g_h1);
    cudaGetSymbolAddress((void**)&whqkv, g_whqkv);
    cudaGetSymbolAddress((void**)&wh1, g_wh1);
    cudaGetSymbolAddress((void**)&wh2, g_wh2);
    cudaGetSymbolAddress((void**)&pahp, g_pah);

    const int smem_g  = 4 * (128 * 72 + 64 * 264) * 2;   // 208896
    const int smem_fa = 5 * 128 * 72 * 2;                // 92160
    cudaFuncSetAttribute(mma_gemm<EPI_QKV, __half>,  cudaFuncAttributeMaxDynamicSharedMemorySize, smem_g);
    cudaFuncSetAttribute(mma_gemm<EPI_GELU, __half>, cudaFuncAttributeMaxDynamicSharedMemorySize, smem_g);
    cudaFuncSetAttribute(mma_gemm<EPI_RES, float>,   cudaFuncAttributeMaxDynamicSharedMemorySize, smem_g);
    cudaFuncSetAttribute(flash_kernel, cudaFuncAttributeMaxDynamicSharedMemorySize, smem_fa);

    const int rows = Bq * Nq;  // 8192

    cudaLaunchAttribute pattr[1];
    pattr[0].id = cudaLaunchAttributeProgrammaticStreamSerialization;
    pattr[0].val.programmaticStreamSerializationAllowed = 1;

    // 0) prep: weight/prior casts + LN1 fused in one kernel
    prep_kernel<<<CAST_BLOCKS + LN_BLOCKS, 256>>>(
        Wqkv, w1, w2, prior, alpha, x, ln1_g, ln1_b,
        whqkv, wh1, wh2, pahp, zp);

    // 1) qkv = z @ Wqkv + bqkv  (q pre-scaled by F*log2e)
    {
        cudaLaunchConfig_t cfg{};
        cfg.gridDim = dim3(3 * Dq / 256, rows / 128); cfg.blockDim = dim3(256);
        cfg.dynamicSmemBytes = smem_g; cfg.attrs = pattr; cfg.numAttrs = 1;
        cudaLaunchKernelEx(&cfg, mma_gemm<EPI_QKV, __half>,
                           (const __half*)zp, (int)Dq, (const __half*)whqkv, (int)(3 * Dq),
                           (__half*)qkvp, (int)(3 * Dq), (int)Dq, bqkv, (const float*)nullptr);
    }
    // 2) fused attention
    {
        cudaLaunchConfig_t cfg{};
        cfg.gridDim = dim3(Nq / 128, Bq * Hq); cfg.blockDim = dim3(256);
        cfg.dynamicSmemBytes = smem_fa; cfg.attrs = pattr; cfg.numAttrs = 1;
        cudaLaunchKernelEx(&cfg, flash_kernel,
                           (const __half*)qkvp, (const __half*)pahp, x, (float*)s1p);
    }
    // 3) z = LN2(s1)
    {
        cudaLaunchConfig_t cfg{};
        cfg.gridDim = dim3(rows / 8); cfg.blockDim = dim3(256);
        cfg.attrs = pattr; cfg.numAttrs = 1;
        cudaLaunchKernelEx(&cfg, ln_kernel, (const float*)s1p, ln2_g, ln2_b, (__half*)zp);
    }
    // 4) h1 = gelu(z @ w1 + b1)
    {
        cudaLaunchConfig_t cfg{};
        cfg.gridDim = dim3(DFFq / 256, rows / 128); cfg.blockDim = dim3(256);
        cfg.dynamicSmemBytes = smem_g; cfg.attrs = pattr; cfg.numAttrs = 1;
        cudaLaunchKernelEx(&cfg, mma_gemm<EPI_GELU, __half>,
                           (const __half*)zp, (int)Dq, (const __half*)wh1, (int)DFFq,
                           (__half*)h1p, (int)DFFq, (int)Dq, b1, (const float*)nullptr);
    }
    // 5) out = s1 + h1 @ w2 + b2
    {
        cudaLaunchConfig_t cfg{};
        cfg.gridDim = dim3(Dq / 256, rows / 128); cfg.blockDim = dim3(256);
        cfg.dynamicSmemBytes = smem_g; cfg.attrs = pattr; cfg.numAttrs = 1;
        cudaLaunchKernelEx(&cfg, mma_gemm<EPI_RES, float>,
                           (const __half*)h1p, (int)DFFq, (const __half*)wh2, (int)Dq,
                           out, (int)Dq, (int)DFFq, b2, (const float*)s1p);
    }
}

// round 14
// speedup vs baseline: 1.0372x; 1.0084x over previous
#include <cuda_runtime.h>
#include <cuda_fp16.h>
#include <math.h>
#include <stdint.h>

// ---------------- problem constants ----------------
#define Bq   8
#define Nq   1024
#define Dq   1024
#define Hq   16
#define DFFq 4096
#define FACTORq 0.125f
#define QSCALE 0.18033688f   // 0.125 * log2(e)

// ---------------- scratch (device globals) ----------------
__device__ __half g_z[(size_t)Bq * Nq * Dq];
__device__ __half g_qkv[(size_t)Bq * Nq * 3 * Dq];
__device__ float  g_s1[(size_t)Bq * Nq * Dq];
__device__ __half g_h1[(size_t)Bq * Nq * DFFq];
__device__ __half g_whqkv[(size_t)Dq * 3 * Dq];
__device__ __half g_wh1[(size_t)Dq * DFFq];
__device__ __half g_wh2[(size_t)DFFq * Dq];
__device__ __half g_pah[(size_t)Bq * Nq * Nq];   // prior * alpha*F*log2e, half

#define EPI_QKV    0
#define EPI_GELU   1
#define EPI_RES    2

// ---------------- PTX helpers (sm_90+ generic ISA only) ----------------
__device__ __forceinline__ uint32_t smem_u32(const void* p) {
    uint32_t a;
    asm("{ .reg .u64 t; cvta.to.shared.u64 t, %1; cvt.u32.u64 %0, t; }" : "=r"(a) : "l"(p));
    return a;
}
__device__ __forceinline__ void cp16(uint32_t s, const void* g) {
    asm volatile("cp.async.cg.shared.global [%0], [%1], 16;" :: "r"(s), "l"(g));
}
__device__ __forceinline__ void cp_commit() {
    asm volatile("cp.async.commit_group;" ::: "memory");
}
template <int N>
__device__ __forceinline__ void cp_wait() {
    asm volatile("cp.async.wait_group %0;" :: "n"(N) : "memory");
}
__device__ __forceinline__ void gdc_wait() {
    asm volatile("griddepcontrol.wait;" ::: "memory");
}
__device__ __forceinline__ void gdc_launch() {
    asm volatile("griddepcontrol.launch_dependents;");
}
__device__ __forceinline__ void ldm4(uint32_t& r0, uint32_t& r1, uint32_t& r2, uint32_t& r3,
                                     uint32_t addr) {
    asm volatile("ldmatrix.sync.aligned.m8n8.x4.shared.b16 {%0,%1,%2,%3}, [%4];"
                 : "=r"(r0), "=r"(r1), "=r"(r2), "=r"(r3) : "r"(addr));
}
__device__ __forceinline__ void ldm4t(uint32_t& r0, uint32_t& r1, uint32_t& r2, uint32_t& r3,
                                      uint32_t addr) {
    asm volatile("ldmatrix.sync.aligned.m8n8.x4.trans.shared.b16 {%0,%1,%2,%3}, [%4];"
                 : "=r"(r0), "=r"(r1), "=r"(r2), "=r"(r3) : "r"(addr));
}
__device__ __forceinline__ void mma_f16(float* d, const uint32_t* a, const uint32_t* b) {
    asm volatile(
        "mma.sync.aligned.m16n8k16.row.col.f32.f16.f16.f32 "
        "{%0,%1,%2,%3}, {%4,%5,%6,%7}, {%8,%9}, {%0,%1,%2,%3};"
        : "+f"(d[0]), "+f"(d[1]), "+f"(d[2]), "+f"(d[3])
        : "r"(a[0]), "r"(a[1]), "r"(a[2]), "r"(a[3]), "r"(b[0]), "r"(b[1]));
}
// f16-accumulate variant (output packed like next MMA's A fragments).
__device__ __forceinline__ void mma_f16h(uint32_t* d, const uint32_t* a, const uint32_t* b) {
    asm volatile(
        "mma.sync.aligned.m16n8k16.row.col.f16.f16.f16.f16 "
        "{%0,%1}, {%2,%3,%4,%5}, {%6,%7}, {%0,%1};"
        : "+r"(d[0]), "+r"(d[1])
        : "r"(a[0]), "r"(a[1]), "r"(a[2]), "r"(a[3]), "r"(b[0]), "r"(b[1]));
}
__device__ __forceinline__ uint32_t hadd2u(uint32_t a, uint32_t b) {
    uint32_t r;
    asm("add.rn.f16x2 %0, %1, %2;" : "=r"(r) : "r"(a), "r"(b));
    return r;
}
__device__ __forceinline__ uint32_t ex2h2(uint32_t a) {
    uint32_t r;
    asm("ex2.approx.f16x2 %0, %1;" : "=r"(r) : "r"(a));
    return r;
}
__device__ __forceinline__ float tanh_ap(float x) {
    float r;
    asm("tanh.approx.f32 %0, %1;" : "=f"(r) : "f"(x));
    return r;
}
__device__ __forceinline__ uint32_t packh2(float a, float b) {
    __half2 h = __floats2half2_rn(a, b);
    return *(uint32_t*)&h;
}
__device__ __forceinline__ float gelu_fast(float x) {
    float x3 = x * x * x;
    return 0.5f * x * (1.0f + tanh_ap(0.7978845608028654f * (x + 0.044715f * x3)));
}

// ---------------------------------------------------------------------------
// Combined cast: weights fp32->half, prior fp32 -> half*(alpha*F*log2e)
// ---------------------------------------------------------------------------
#define SEG0 786432
#define SEG1 (SEG0 + 1048576)
#define SEG2 (SEG1 + 1048576)
#define SEG3 (SEG2 + 2097152)
__global__ void __launch_bounds__(256)
cast_all_kernel(const float* __restrict__ wqkv, const float* __restrict__ w1,
                const float* __restrict__ w2, const float* __restrict__ prior,
                const float* __restrict__ alpha,
                __half* __restrict__ hq, __half* __restrict__ h1,
                __half* __restrict__ h2, __half* __restrict__ hp)
{
    const int i = blockIdx.x * 256 + threadIdx.x;
    const float* src;
    __half* dst;
    int li;
    float sc = 1.0f;
    if (i < SEG0)      { src = wqkv;  dst = hq; li = i; }
    else if (i < SEG1) { src = w1;    dst = h1; li = i - SEG0; }
    else if (i < SEG2) { src = w2;    dst = h2; li = i - SEG1; }
    else               { src = prior; dst = hp; li = i - SEG2; sc = alpha[0] * QSCALE; }
    float4 v = ((const float4*)src)[li];
    uint2 u;
    u.x = packh2(v.x * sc, v.y * sc);
    u.y = packh2(v.z * sc, v.w * sc);
    ((uint2*)dst)[li] = u;
}

// ---------------------------------------------------------------------------
// LayerNorm, warp-per-row (PDL: launch_dependents at top).
// ---------------------------------------------------------------------------
__global__ void __launch_bounds__(256)
ln_kernel(const float* __restrict__ x, const float* __restrict__ g,
          const float* __restrict__ bb, __half* __restrict__ out)
{
    gdc_launch();
    gdc_wait();
    const int warp = threadIdx.x >> 5, lane = threadIdx.x & 31;
    const int row = blockIdx.x * 8 + warp;
    const float4* xr = (const float4*)(x + (size_t)row * Dq);

    float4 v[8];
    float s = 0.0f, s2 = 0.0f;
#pragma unroll
    for (int t = 0; t < 8; t++) {
        v[t] = xr[lane + t * 32];
        s += v[t].x + v[t].y + v[t].z + v[t].w;
        s2 += v[t].x * v[t].x + v[t].y * v[t].y + v[t].z * v[t].z + v[t].w * v[t].w;
    }
#pragma unroll
    for (int o = 16; o; o >>= 1) {
        s += __shfl_xor_sync(0xffffffffu, s, o);
        s2 += __shfl_xor_sync(0xffffffffu, s2, o);
    }
    const float mu = s * (1.0f / Dq);
    const float var = s2 * (1.0f / Dq) - mu * mu;
    const float inv = rsqrtf(var + 1e-5f);

    __half* orow = out + (size_t)row * Dq;
#pragma unroll
    for (int t = 0; t < 8; t++) {
        const int i = (lane + t * 32) * 4;
        float4 gg = *(const float4*)&g[i];
        float4 bv = *(const float4*)&bb[i];
        uint2 u;
        u.x = packh2((v[t].x - mu) * inv * gg.x + bv.x, (v[t].y - mu) * inv * gg.y + bv.y);
        u.y = packh2((v[t].z - mu) * inv * gg.z + bv.z, (v[t].w - mu) * inv * gg.w + bv.w);
        *(uint2*)&orow[i] = u;
    }
}

// ---------------------------------------------------------------------------
// Flash attention v4: 4 warps x 32 q-rows (128 threads), 2 CTAs/SM.
// Halves per-SM ldmatrix traffic vs 8x16 shape; reg cap 256 -> no spills.
// grid = (N/128, B*H).
// ---------------------------------------------------------------------------
__global__ void __launch_bounds__(128, 2)
flash_kernel(const __half* __restrict__ qkv,
             const __half* __restrict__ pah,
             const float* __restrict__ x,
             float* __restrict__ s1)
{
    constexpr int LDR = 72;
    constexpr int TH = 128 * LDR;
    extern __shared__ __half sm[];
    const uint32_t ub = smem_u32(sm);

    const int tid = threadIdx.x;
    const int lane = tid & 31;
    const int wid = tid >> 5;           // 0..3
    const int gid = lane >> 2, tig = lane & 3;

    const int qt = blockIdx.x;
    const int bh = blockIdx.y;
    const int b = bh >> 4, h = bh & 15;
    const int q0 = qt * 128;

    const __half* qbase = qkv + (size_t)b * Nq * (3 * Dq) + (size_t)h * 64;
    const __half* kbase = qbase + Dq;
    const __half* vbase = qbase + 2 * Dq;

    gdc_wait();

    auto load_q = [&]() {
#pragma unroll
        for (int t = 0; t < 8; t++) {
            int id = tid + t * 128;
            int r = id >> 3, j = id & 7;
            cp16(ub + (uint32_t)(r * LDR + j * 8) * 2u,
                 qbase + (size_t)(q0 + r) * (3 * Dq) + j * 8);
        }
    };
    auto load_kv = [&](int i) {
        const int kv0 = i * 128;
        const uint32_t sk = ub + (uint32_t)(TH * (1 + 2 * (i & 1))) * 2u;
        const uint32_t sv = sk + (uint32_t)TH * 2u;
#pragma unroll
        for (int t = 0; t < 8; t++) {
            int id = tid + t * 128;
            int r = id >> 3, j = id & 7;
            cp16(sk + (uint32_t)(r * LDR + j * 8) * 2u,
                 kbase + (size_t)(kv0 + r) * (3 * Dq) + j * 8);
        }
#pragma unroll
        for (int t = 0; t < 8; t++) {
            int id = tid + t * 128;
            int r = id >> 3, j = id & 7;
            cp16(sv + (uint32_t)(r * LDR + j * 8) * 2u,
                 vbase + (size_t)(kv0 + r) * (3 * Dq) + j * 8);
        }
    };

    load_q();
    load_kv(0);
    cp_commit();

    const uint32_t qa_off = (uint32_t)((wid * 32 + (lane & 15)) * LDR + ((lane >> 4) << 3));
    const uint32_t kb_off = (uint32_t)(((lane & 7) + ((lane >> 4) << 3)) * LDR +
                                       (((lane >> 3) & 1) << 3));
    const uint32_t vb_off = (uint32_t)(((lane & 7) + (((lane >> 3) & 1) << 3)) * LDR +
                                       ((lane >> 4) << 3));

    uint32_t qa[2][4][4];                 // [mf][ks][frag]
    float oacc[2][8][4];                  // [mf][nf][reg]
#pragma unroll
    for (int mf = 0; mf < 2; mf++)
#pragma unroll
        for (int t = 0; t < 8; t++)
#pragma unroll
            for (int q = 0; q < 4; q++) oacc[mf][t][q] = 0.0f;
    float lacc[2][4] = {{0, 0, 0, 0}, {0, 0, 0, 0}};
    const uint32_t ONES = 0x3C003C00u;
    const uint32_t b_ones[2] = {ONES, ONES};

    const __half* prbase = pah + (size_t)b * Nq * Nq +
                           (size_t)(q0 + wid * 32 + gid) * Nq;

    for (int i = 0; i < 8; i++) {
        cp_wait<0>();
        __syncthreads();
        if (i == 0) {
#pragma unroll
            for (int mf = 0; mf < 2; mf++)
#pragma unroll
                for (int ks = 0; ks < 4; ks++)
                    ldm4(qa[mf][ks][0], qa[mf][ks][1], qa[mf][ks][2], qa[mf][ks][3],
                         ub + (qa_off + (uint32_t)(mf * 16 * LDR + ks * 16)) * 2u);
        }
        if (i < 7) {
            load_kv(i + 1);
            cp_commit();
        }

        const uint32_t sk = ub + (uint32_t)(TH * (1 + 2 * (i & 1))) * 2u;
        const uint32_t sv = sk + (uint32_t)TH * 2u;

#pragma unroll
        for (int nb = 0; nb < 8; nb++) {
            // ---- S = Q K^T for this 16-col nb block (f16 accum) ----
            uint32_t s2[2][2][2];
#pragma unroll
            for (int mf = 0; mf < 2; mf++) {
                s2[mf][0][0] = 0u; s2[mf][0][1] = 0u;
                s2[mf][1][0] = 0u; s2[mf][1][1] = 0u;
            }
#pragma unroll
            for (int ks = 0; ks < 4; ks++) {
                uint32_t r0, r1, r2, r3;
                ldm4(r0, r1, r2, r3,
                     sk + (kb_off + (uint32_t)(nb * 16 * LDR + ks * 16)) * 2u);
                uint32_t b01[2] = {r0, r1}, b23[2] = {r2, r3};
#pragma unroll
                for (int mf = 0; mf < 2; mf++) {
                    mma_f16h(s2[mf][0], qa[mf][ks], b01);
                    mma_f16h(s2[mf][1], qa[mf][ks], b23);
                }
            }

            // ---- P = 2^(S + pah) ----
            const int kvc = i * 128 + nb * 16 + tig * 2;
#pragma unroll
            for (int mf = 0; mf < 2; mf++) {
                const __half* pr = prbase + (size_t)(mf * 16) * Nq + kvc;
                uint32_t p00 = *(const uint32_t*)pr;
                uint32_t p01 = *(const uint32_t*)(pr + 8 * Nq);
                uint32_t p10 = *(const uint32_t*)(pr + 8);
                uint32_t p11 = *(const uint32_t*)(pr + 8 * Nq + 8);
                s2[mf][0][0] = ex2h2(hadd2u(s2[mf][0][0], p00));
                s2[mf][0][1] = ex2h2(hadd2u(s2[mf][0][1], p01));
                s2[mf][1][0] = ex2h2(hadd2u(s2[mf][1][0], p10));
                s2[mf][1][1] = ex2h2(hadd2u(s2[mf][1][1], p11));
            }

            // ---- l += P @ ones ;  O += P V ----
            uint32_t pa0[4] = {s2[0][0][0], s2[0][0][1], s2[0][1][0], s2[0][1][1]};
            uint32_t pa1[4] = {s2[1][0][0], s2[1][0][1], s2[1][1][0], s2[1][1][1]};
            mma_f16(lacc[0], pa0, b_ones);
            mma_f16(lacc[1], pa1, b_ones);
#pragma unroll
            for (int c = 0; c < 4; c++) {
                uint32_t r0, r1, r2, r3;
                ldm4t(r0, r1, r2, r3,
                      sv + (vb_off + (uint32_t)(nb * 16 * LDR + c * 16)) * 2u);
                uint32_t b01[2] = {r0, r1}, b23[2] = {r2, r3};
                mma_f16(oacc[0][2 * c + 0], pa0, b01);
                mma_f16(oacc[0][2 * c + 1], pa0, b23);
                mma_f16(oacc[1][2 * c + 0], pa1, b01);
                mma_f16(oacc[1][2 * c + 1], pa1, b23);
            }
        }
    }

    gdc_launch();

#pragma unroll
    for (int mf = 0; mf < 2; mf++) {
        const float inv0 = 1.0f / lacc[mf][0], inv1 = 1.0f / lacc[mf][2];
        const int gr0 = q0 + wid * 32 + mf * 16 + gid;
        const size_t o0 = (size_t)b * Nq * Dq + (size_t)gr0 * Dq + h * 64 + tig * 2;
        const size_t o1 = o0 + (size_t)8 * Dq;
#pragma unroll
        for (int t = 0; t < 8; t++) {
            float2 x0 = *(const float2*)(x + o0 + t * 8);
            float2 x1 = *(const float2*)(x + o1 + t * 8);
            float2 w0 = make_float2(oacc[mf][t][0] * inv0 + x0.x,
                                    oacc[mf][t][1] * inv0 + x0.y);
            float2 w1 = make_float2(oacc[mf][t][2] * inv1 + x1.x,
                                    oacc[mf][t][3] * inv1 + x1.y);
            *(float2*)(s1 + o0 + t * 8) = w0;
            *(float2*)(s1 + o1 + t * 8) = w1;
        }
    }
}

// ---------------------------------------------------------------------------
// fp16 mma.sync GEMM (fp32 accum).  BM=128, BN=256, BK=64, 4-stage cp.async.
// A [M,K] half K-major; B [K,N] half row-major (ldmatrix.trans fragments).
// 8 warps 2(M)x4(N); warp tile 64x64.  PDL as before.
// ---------------------------------------------------------------------------
template <int EPI, typename CT>
__global__ void __launch_bounds__(256, 1)
mma_gemm(const __half* __restrict__ A, int lda,
         const __half* __restrict__ B, int ldb,
         CT* __restrict__ C, int ldc, int K,
         const float* __restrict__ e0, const float* __restrict__ e1)
{
    constexpr int BM = 128;
    constexpr int BN = 256;
    constexpr int BK = 64;
    constexpr int S = 4;
    constexpr int LDRA = 72;
    constexpr int LDRB = BN + 8;
    constexpr int AH = BM * LDRA;
    constexpr int BH = BK * LDRB;
    constexpr int STGH = AH + BH;
    constexpr int MF = 4;
    constexpr int NC = 4;

    extern __shared__ __half smh[];
    const uint32_t ubase = smem_u32(smh);

    const int tid = threadIdx.x;
    const int lane = tid & 31;
    const int wid = tid >> 5;
    const int wm = wid >> 2, wn = wid & 3;
    const int gid = lane >> 2, tig = lane & 3;

    const int row0 = blockIdx.y * BM;
    const int col0 = blockIdx.x * BN;
    const int niter = K / BK;

    const uint32_t a_off = (uint32_t)((wm * 64 + (lane & 15)) * LDRA + ((lane >> 4) << 3));
    const uint32_t b_off = (uint32_t)(((lane & 7) + (((lane >> 3) & 1) << 3)) * LDRB +
                                      wn * 64 + ((lane >> 4) << 3));

    auto load_a = [&](int it) {
        const int k0 = it * BK;
        const uint32_t sa = ubase + (uint32_t)((it % S) * STGH) * 2u;
#pragma unroll
        for (int t = 0; t < 4; t++) {
            int id = tid + t * 256;
            int r = id >> 3, j = id & 7;
            cp16(sa + (uint32_t)r * 144u + (uint32_t)j * 16u,
                 A + (size_t)(row0 + r) * lda + k0 + j * 8);
        }
    };
    auto load_b = [&](int it) {
        const int k0 = it * BK;
        const uint32_t sb = ubase + (uint32_t)((it % S) * STGH + AH) * 2u;
#pragma unroll
        for (int t = 0; t < 8; t++) {
            int id = tid + t * 256;
            int r = id >> 5, j = id & 31;
            cp16(sb + (uint32_t)r * (LDRB * 2) + (uint32_t)j * 16u,
                 B + (size_t)(k0 + r) * ldb + col0 + j * 8);
        }
    };

#pragma unroll
    for (int it = 0; it < S - 1; it++) load_b(it);
    gdc_wait();
#pragma unroll
    for (int it = 0; it < S - 1; it++) {
        load_a(it);
        cp_commit();
    }

    float acc[MF][8][4];
#pragma unroll
    for (int mf = 0; mf < MF; mf++)
#pragma unroll
        for (int nf = 0; nf < 8; nf++)
#pragma unroll
            for (int q = 0; q < 4; q++) acc[mf][nf][q] = 0.0f;

    for (int i = 0; i < niter; i++) {
        cp_wait<S - 2>();
        __syncthreads();
        if (i + S - 1 < niter) {
            load_b(i + S - 1);
            load_a(i + S - 1);
        }
        cp_commit();

        const uint32_t sa = ubase + (uint32_t)((i % S) * STGH) * 2u;
        const uint32_t sb = ubase + (uint32_t)((i % S) * STGH + AH) * 2u;

#pragma unroll
        for (int ks = 0; ks < BK / 16; ks++) {
            uint32_t a[MF][4], b[NC][4];
#pragma unroll
            for (int mf = 0; mf < MF; mf++)
                ldm4(a[mf][0], a[mf][1], a[mf][2], a[mf][3],
                     sa + (a_off + (uint32_t)(mf * 16 * LDRA + ks * 16)) * 2u);
#pragma unroll
            for (int c = 0; c < NC; c++)
                ldm4t(b[c][0], b[c][1], b[c][2], b[c][3],
                      sb + (b_off + (uint32_t)(ks * 16 * LDRB + c * 16)) * 2u);
#pragma unroll
            for (int mf = 0; mf < MF; mf++)
#pragma unroll
                for (int c = 0; c < NC; c++) {
                    mma_f16(acc[mf][2 * c + 0], a[mf], &b[c][0]);
                    mma_f16(acc[mf][2 * c + 1], a[mf], &b[c][2]);
                }
        }
    }

    gdc_launch();

#pragma unroll
    for (int mf = 0; mf < MF; mf++) {
        const int gr0 = row0 + wm * 64 + mf * 16 + gid;
#pragma unroll
        for (int nf = 0; nf < 8; nf++) {
            const int gc = col0 + wn * 64 + nf * 8 + tig * 2;
#pragma unroll
            for (int half_ = 0; half_ < 2; half_++) {
                const int gr = gr0 + half_ * 8;
                float v0 = acc[mf][nf][half_ * 2 + 0];
                float v1 = acc[mf][nf][half_ * 2 + 1];
                float o0, o1;
                if constexpr (EPI == EPI_QKV) {
                    o0 = v0 + e0[gc]; o1 = v1 + e0[gc + 1];
                    if (gc < Dq) { o0 *= QSCALE; o1 *= QSCALE; }
                } else if constexpr (EPI == EPI_GELU) {
                    o0 = gelu_fast(v0 + e0[gc]); o1 = gelu_fast(v1 + e0[gc + 1]);
                } else {  // EPI_RES
                    float2 rr = *(const float2*)&e1[(size_t)gr * ldc + gc];
                    o0 = v0 + e0[gc] + rr.x; o1 = v1 + e0[gc + 1] + rr.y;
                }
                if constexpr (sizeof(CT) == 2) {
                    *(__half2*)&C[(size_t)gr * ldc + gc] = __floats2half2_rn(o0, o1);
                } else {
                    *(float2*)&C[(size_t)gr * ldc + gc] = make_float2(o0, o1);
                }
            }
        }
    }
}

// ---------------------------------------------------------------------------
// launch  (exact R11 chain; only flash config differs)
// ---------------------------------------------------------------------------
extern "C" void kernel_launch(void* const* d_in, const int* in_sizes, int n_in,
                              void* d_out, int out_size)
{
    const float* x     = (const float*)d_in[0];
    const float* prior = (const float*)d_in[1];
    const float* Wqkv  = (const float*)d_in[2];
    const float* bqkv  = (const float*)d_in[3];
    const float* alpha = (const float*)d_in[4];
    const float* ln1_g = (const float*)d_in[5];
    const float* ln1_b = (const float*)d_in[6];
    const float* ln2_g = (const float*)d_in[7];
    const float* ln2_b = (const float*)d_in[8];
    const float* w1    = (const float*)d_in[9];
    const float* b1    = (const float*)d_in[10];
    const float* w2    = (const float*)d_in[11];
    const float* b2    = (const float*)d_in[12];
    float* out = (float*)d_out;

    __half *zp, *qkvp, *h1p, *whqkv, *wh1, *wh2, *pahp;
    float* s1p;
    cudaGetSymbolAddress((void**)&zp, g_z);
    cudaGetSymbolAddress((void**)&qkvp, g_qkv);
    cudaGetSymbolAddress((void**)&s1p, g_s1);
    cudaGetSymbolAddress((void**)&h1p, g_h1);
    cudaGetSymbolAddress((void**)&whqkv, g_whqkv);
    cudaGetSymbolAddress((void**)&wh1, g_wh1);
    cudaGetSymbolAddress((void**)&wh2, g_wh2);
    cudaGetSymbolAddress((void**)&pahp, g_pah);

    const int smem_g  = 4 * (128 * 72 + 64 * 264) * 2;   // 208896
    const int smem_fa = 5 * 128 * 72 * 2;                // 92160
    cudaFuncSetAttribute(mma_gemm<EPI_QKV, __half>,  cudaFuncAttributeMaxDynamicSharedMemorySize, smem_g);
    cudaFuncSetAttribute(mma_gemm<EPI_GELU, __half>, cudaFuncAttributeMaxDynamicSharedMemorySize, smem_g);
    cudaFuncSetAttribute(mma_gemm<EPI_RES, float>,   cudaFuncAttributeMaxDynamicSharedMemorySize, smem_g);
    cudaFuncSetAttribute(flash_kernel, cudaFuncAttributeMaxDynamicSharedMemorySize, smem_fa);

    const int rows = Bq * Nq;  // 8192

    cudaLaunchAttribute pattr[1];
    pattr[0].id = cudaLaunchAttributeProgrammaticStreamSerialization;
    pattr[0].val.programmaticStreamSerializationAllowed = 1;

    // 0) all casts in one kernel
    cast_all_kernel<<<SEG3 / 256, 256>>>(Wqkv, w1, w2, prior, alpha,
                                         whqkv, wh1, wh2, pahp);

    // 1) z = LN1(x)
    {
        cudaLaunchConfig_t cfg{};
        cfg.gridDim = dim3(rows / 8); cfg.blockDim = dim3(256);
        cfg.attrs = pattr; cfg.numAttrs = 1;
        cudaLaunchKernelEx(&cfg, ln_kernel, x, ln1_g, ln1_b, (__half*)zp);
    }
    // 2) qkv = z @ Wqkv + bqkv
    {
        cudaLaunchConfig_t cfg{};
        cfg.gridDim = dim3(3 * Dq / 256, rows / 128); cfg.blockDim = dim3(256);
        cfg.dynamicSmemBytes = smem_g; cfg.attrs = pattr; cfg.numAttrs = 1;
        cudaLaunchKernelEx(&cfg, mma_gemm<EPI_QKV, __half>,
                           (const __half*)zp, (int)Dq, (const __half*)whqkv, (int)(3 * Dq),
                           (__half*)qkvp, (int)(3 * Dq), (int)Dq, bqkv, (const float*)nullptr);
    }
    // 3) fused attention (4 warps x 32 q-rows)
    {
        cudaLaunchConfig_t cfg{};
        cfg.gridDim = dim3(Nq / 128, Bq * Hq); cfg.blockDim = dim3(128);
        cfg.dynamicSmemBytes = smem_fa; cfg.attrs = pattr; cfg.numAttrs = 1;
        cudaLaunchKernelEx(&cfg, flash_kernel,
                           (const __half*)qkvp, (const __half*)pahp, x, (float*)s1p);
    }
    // 4) z = LN2(s1)
    {
        cudaLaunchConfig_t cfg{};
        cfg.gridDim = dim3(rows / 8); cfg.blockDim = dim3(256);
        cfg.attrs = pattr; cfg.numAttrs = 1;
        cudaLaunchKernelEx(&cfg, ln_kernel, (const float*)s1p, ln2_g, ln2_b, (__half*)zp);
    }
    // 5) h1 = gelu(z @ w1 + b1)
    {
        cudaLaunchConfig_t cfg{};
        cfg.gridDim = dim3(DFFq / 256, rows / 128); cfg.blockDim = dim3(256);
        cfg.dynamicSmemBytes = smem_g; cfg.attrs = pattr; cfg.numAttrs = 1;
        cudaLaunchKernelEx(&cfg, mma_gemm<EPI_GELU, __half>,
                           (const __half*)zp, (int)Dq, (const __half*)wh1, (int)DFFq,
                           (__half*)h1p, (int)DFFq, (int)Dq, b1, (const float*)nullptr);
    }
    // 6) out = s1 + h1 @ w2 + b2
    {
        cudaLaunchConfig_t cfg{};
        cfg.gridDim = dim3(Dq / 256, rows / 128); cfg.blockDim = dim3(256);
        cfg.dynamicSmemBytes = smem_g; cfg.attrs = pattr; cfg.numAttrs = 1;
        cudaLaunchKernelEx(&cfg, mma_gemm<EPI_RES, float>,
                           (const __half*)h1p, (int)DFFq, (const __half*)wh2, (int)Dq,
                           out, (int)Dq, (int)DFFq, b2, (const float*)s1p);
    }
}

// round 15
// speedup vs baseline: 1.0416x; 1.0043x over previous
#include <cuda_runtime.h>
#include <cuda_fp16.h>
#include <math.h>
#include <stdint.h>

// ---------------- problem constants ----------------
#define Bq   8
#define Nq   1024
#define Dq   1024
#define Hq   16
#define DFFq 4096
#define FACTORq 0.125f
#define QSCALE 0.18033688f   // 0.125 * log2(e)

// ---------------- scratch (device globals) ----------------
__device__ __half g_z[(size_t)Bq * Nq * Dq];
__device__ __half g_qkv[(size_t)Bq * Nq * 3 * Dq];
__device__ float  g_s1[(size_t)Bq * Nq * Dq];
__device__ __half g_h1[(size_t)Bq * Nq * DFFq];
__device__ __half g_whqkv[(size_t)Dq * 3 * Dq];
__device__ __half g_wh1[(size_t)Dq * DFFq];
__device__ __half g_wh2[(size_t)DFFq * Dq];
__device__ __half g_pah[(size_t)Bq * Nq * Nq];   // prior * alpha*F*log2e, half

#define EPI_QKV    0
#define EPI_GELU   1
#define EPI_RES    2

// ---------------- PTX helpers (sm_90+ generic ISA only) ----------------
__device__ __forceinline__ uint32_t smem_u32(const void* p) {
    uint32_t a;
    asm("{ .reg .u64 t; cvta.to.shared.u64 t, %1; cvt.u32.u64 %0, t; }" : "=r"(a) : "l"(p));
    return a;
}
__device__ __forceinline__ void cp16(uint32_t s, const void* g) {
    asm volatile("cp.async.cg.shared.global [%0], [%1], 16;" :: "r"(s), "l"(g));
}
__device__ __forceinline__ void cp_commit() {
    asm volatile("cp.async.commit_group;" ::: "memory");
}
template <int N>
__device__ __forceinline__ void cp_wait() {
    asm volatile("cp.async.wait_group %0;" :: "n"(N) : "memory");
}
__device__ __forceinline__ void gdc_wait() {
    asm volatile("griddepcontrol.wait;" ::: "memory");
}
__device__ __forceinline__ void gdc_launch() {
    asm volatile("griddepcontrol.launch_dependents;");
}
__device__ __forceinline__ void ldm4(uint32_t& r0, uint32_t& r1, uint32_t& r2, uint32_t& r3,
                                     uint32_t addr) {
    asm volatile("ldmatrix.sync.aligned.m8n8.x4.shared.b16 {%0,%1,%2,%3}, [%4];"
                 : "=r"(r0), "=r"(r1), "=r"(r2), "=r"(r3) : "r"(addr));
}
__device__ __forceinline__ void ldm4t(uint32_t& r0, uint32_t& r1, uint32_t& r2, uint32_t& r3,
                                      uint32_t addr) {
    asm volatile("ldmatrix.sync.aligned.m8n8.x4.trans.shared.b16 {%0,%1,%2,%3}, [%4];"
                 : "=r"(r0), "=r"(r1), "=r"(r2), "=r"(r3) : "r"(addr));
}
__device__ __forceinline__ void mma_f16(float* d, const uint32_t* a, const uint32_t* b) {
    asm volatile(
        "mma.sync.aligned.m16n8k16.row.col.f32.f16.f16.f32 "
        "{%0,%1,%2,%3}, {%4,%5,%6,%7}, {%8,%9}, {%0,%1,%2,%3};"
        : "+f"(d[0]), "+f"(d[1]), "+f"(d[2]), "+f"(d[3])
        : "r"(a[0]), "r"(a[1]), "r"(a[2]), "r"(a[3]), "r"(b[0]), "r"(b[1]));
}
// f16-accumulate variant (output packed like next MMA's A fragments).
__device__ __forceinline__ void mma_f16h(uint32_t* d, const uint32_t* a, const uint32_t* b) {
    asm volatile(
        "mma.sync.aligned.m16n8k16.row.col.f16.f16.f16.f16 "
        "{%0,%1}, {%2,%3,%4,%5}, {%6,%7}, {%0,%1};"
        : "+r"(d[0]), "+r"(d[1])
        : "r"(a[0]), "r"(a[1]), "r"(a[2]), "r"(a[3]), "r"(b[0]), "r"(b[1]));
}
__device__ __forceinline__ uint32_t hadd2u(uint32_t a, uint32_t b) {
    uint32_t r;
    asm("add.rn.f16x2 %0, %1, %2;" : "=r"(r) : "r"(a), "r"(b));
    return r;
}
__device__ __forceinline__ uint32_t ex2h2(uint32_t a) {
    uint32_t r;
    asm("ex2.approx.f16x2 %0, %1;" : "=r"(r) : "r"(a));
    return r;
}
__device__ __forceinline__ float tanh_ap(float x) {
    float r;
    asm("tanh.approx.f32 %0, %1;" : "=f"(r) : "f"(x));
    return r;
}
__device__ __forceinline__ uint32_t packh2(float a, float b) {
    __half2 h = __floats2half2_rn(a, b);
    return *(uint32_t*)&h;
}
__device__ __forceinline__ float gelu_fast(float x) {
    float x3 = x * x * x;
    return 0.5f * x * (1.0f + tanh_ap(0.7978845608028654f * (x + 0.044715f * x3)));
}

// ---------------------------------------------------------------------------
// Prep kernel: LN1 blocks FIRST (hide inside cast waves), then casts.
// ---------------------------------------------------------------------------
#define SEG0 786432
#define SEG1 (SEG0 + 1048576)
#define SEG2 (SEG1 + 1048576)
#define SEG3 (SEG2 + 2097152)
#define LN_BLOCKS (Bq * Nq / 8)       // 1024
#define CAST_BLOCKS (SEG3 / 256)      // 19456
__global__ void __launch_bounds__(256)
prep_kernel(const float* __restrict__ wqkv, const float* __restrict__ w1,
            const float* __restrict__ w2, const float* __restrict__ prior,
            const float* __restrict__ alpha,
            const float* __restrict__ x, const float* __restrict__ ln_g,
            const float* __restrict__ ln_b,
            __half* __restrict__ hq, __half* __restrict__ h1,
            __half* __restrict__ h2, __half* __restrict__ hp,
            __half* __restrict__ z)
{
    if (blockIdx.x >= LN_BLOCKS) {
        const int i = (blockIdx.x - LN_BLOCKS) * 256 + threadIdx.x;
        const float* src;
        __half* dst;
        int li;
        float sc = 1.0f;
        if (i < SEG0)      { src = wqkv;  dst = hq; li = i; }
        else if (i < SEG1) { src = w1;    dst = h1; li = i - SEG0; }
        else if (i < SEG2) { src = w2;    dst = h2; li = i - SEG1; }
        else               { src = prior; dst = hp; li = i - SEG2; sc = alpha[0] * QSCALE; }
        float4 v = ((const float4*)src)[li];
        uint2 u;
        u.x = packh2(v.x * sc, v.y * sc);
        u.y = packh2(v.z * sc, v.w * sc);
        ((uint2*)dst)[li] = u;
        return;
    }
    // ---- LN1 segment (scheduled first) ----
    const int warp = threadIdx.x >> 5, lane = threadIdx.x & 31;
    const int row = blockIdx.x * 8 + warp;
    const float4* xr = (const float4*)(x + (size_t)row * Dq);

    float4 v[8];
    float s = 0.0f, s2 = 0.0f;
#pragma unroll
    for (int t = 0; t < 8; t++) {
        v[t] = xr[lane + t * 32];
        s += v[t].x + v[t].y + v[t].z + v[t].w;
        s2 += v[t].x * v[t].x + v[t].y * v[t].y + v[t].z * v[t].z + v[t].w * v[t].w;
    }
#pragma unroll
    for (int o = 16; o; o >>= 1) {
        s += __shfl_xor_sync(0xffffffffu, s, o);
        s2 += __shfl_xor_sync(0xffffffffu, s2, o);
    }
    const float mu = s * (1.0f / Dq);
    const float var = s2 * (1.0f / Dq) - mu * mu;
    const float inv = rsqrtf(var + 1e-5f);

    __half* orow = z + (size_t)row * Dq;
#pragma unroll
    for (int t = 0; t < 8; t++) {
        const int i = (lane + t * 32) * 4;
        float4 gg = *(const float4*)&ln_g[i];
        float4 bv = *(const float4*)&ln_b[i];
        uint2 u;
        u.x = packh2((v[t].x - mu) * inv * gg.x + bv.x, (v[t].y - mu) * inv * gg.y + bv.y);
        u.y = packh2((v[t].z - mu) * inv * gg.z + bv.z, (v[t].w - mu) * inv * gg.w + bv.w);
        *(uint2*)&orow[i] = u;
    }
}

// ---------------------------------------------------------------------------
// LayerNorm, warp-per-row (LN2).
// ---------------------------------------------------------------------------
__global__ void __launch_bounds__(256)
ln_kernel(const float* __restrict__ x, const float* __restrict__ g,
          const float* __restrict__ bb, __half* __restrict__ out)
{
    gdc_launch();
    gdc_wait();
    const int warp = threadIdx.x >> 5, lane = threadIdx.x & 31;
    const int row = blockIdx.x * 8 + warp;
    const float4* xr = (const float4*)(x + (size_t)row * Dq);

    float4 v[8];
    float s = 0.0f, s2 = 0.0f;
#pragma unroll
    for (int t = 0; t < 8; t++) {
        v[t] = xr[lane + t * 32];
        s += v[t].x + v[t].y + v[t].z + v[t].w;
        s2 += v[t].x * v[t].x + v[t].y * v[t].y + v[t].z * v[t].z + v[t].w * v[t].w;
    }
#pragma unroll
    for (int o = 16; o; o >>= 1) {
        s += __shfl_xor_sync(0xffffffffu, s, o);
        s2 += __shfl_xor_sync(0xffffffffu, s2, o);
    }
    const float mu = s * (1.0f / Dq);
    const float var = s2 * (1.0f / Dq) - mu * mu;
    const float inv = rsqrtf(var + 1e-5f);

    __half* orow = out + (size_t)row * Dq;
#pragma unroll
    for (int t = 0; t < 8; t++) {
        const int i = (lane + t * 32) * 4;
        float4 gg = *(const float4*)&g[i];
        float4 bv = *(const float4*)&bb[i];
        uint2 u;
        u.x = packh2((v[t].x - mu) * inv * gg.x + bv.x, (v[t].y - mu) * inv * gg.y + bv.y);
        u.y = packh2((v[t].z - mu) * inv * gg.z + bv.z, (v[t].w - mu) * inv * gg.w + bv.w);
        *(uint2*)&orow[i] = u;
    }
}

// ---------------------------------------------------------------------------
// Flash attention (exact R11 config): half2 softmax, 2 CTAs/SM, 8 warps x 16
// q-rows, kv tile in two nb-halves.  grid = (N/128, B*H), 256 threads.
// ---------------------------------------------------------------------------
__global__ void __launch_bounds__(256, 2)
flash_kernel(const __half* __restrict__ qkv,
             const __half* __restrict__ pah,
             const float* __restrict__ x,
             float* __restrict__ s1)
{
    constexpr int LDR = 72;
    constexpr int TH = 128 * LDR;
    extern __shared__ __half sm[];
    const uint32_t ub = smem_u32(sm);

    const int tid = threadIdx.x;
    const int lane = tid & 31;
    const int wid = tid >> 5;
    const int gid = lane >> 2, tig = lane & 3;

    const int qt = blockIdx.x;
    const int bh = blockIdx.y;
    const int b = bh >> 4, h = bh & 15;
    const int q0 = qt * 128;

    const __half* qbase = qkv + (size_t)b * Nq * (3 * Dq) + (size_t)h * 64;
    const __half* kbase = qbase + Dq;
    const __half* vbase = qbase + 2 * Dq;

    gdc_wait();

    auto load_q = [&]() {
#pragma unroll
        for (int t = 0; t < 4; t++) {
            int id = tid + t * 256;
            int r = id >> 3, j = id & 7;
            cp16(ub + (uint32_t)(r * LDR + j * 8) * 2u,
                 qbase + (size_t)(q0 + r) * (3 * Dq) + j * 8);
        }
    };
    auto load_kv = [&](int i) {
        const int kv0 = i * 128;
        const uint32_t sk = ub + (uint32_t)(TH * (1 + 2 * (i & 1))) * 2u;
        const uint32_t sv = sk + (uint32_t)TH * 2u;
#pragma unroll
        for (int t = 0; t < 4; t++) {
            int id = tid + t * 256;
            int r = id >> 3, j = id & 7;
            cp16(sk + (uint32_t)(r * LDR + j * 8) * 2u,
                 kbase + (size_t)(kv0 + r) * (3 * Dq) + j * 8);
        }
#pragma unroll
        for (int t = 0; t < 4; t++) {
            int id = tid + t * 256;
            int r = id >> 3, j = id & 7;
            cp16(sv + (uint32_t)(r * LDR + j * 8) * 2u,
                 vbase + (size_t)(kv0 + r) * (3 * Dq) + j * 8);
        }
    };

    load_q();
    load_kv(0);
    cp_commit();

    const uint32_t qa_off = (uint32_t)((wid * 16 + (lane & 15)) * LDR + ((lane >> 4) << 3));
    const uint32_t kb_off = (uint32_t)(((lane & 7) + ((lane >> 4) << 3)) * LDR +
                                       (((lane >> 3) & 1) << 3));
    const uint32_t vb_off = (uint32_t)(((lane & 7) + (((lane >> 3) & 1) << 3)) * LDR +
                                       ((lane >> 4) << 3));

    uint32_t qa[4][4];
    float oacc[8][4];
#pragma unroll
    for (int t = 0; t < 8; t++)
#pragma unroll
        for (int q = 0; q < 4; q++) oacc[t][q] = 0.0f;
    float lacc[4] = {0.0f, 0.0f, 0.0f, 0.0f};
    const uint32_t ONES = 0x3C003C00u;
    const uint32_t b_ones[2] = {ONES, ONES};

    const __half* prh0 = pah + (size_t)b * Nq * Nq + (size_t)(q0 + wid * 16 + gid) * Nq;
    const __half* prh1 = prh0 + 8 * Nq;

    for (int i = 0; i < 8; i++) {
        cp_wait<0>();
        __syncthreads();
        if (i == 0) {
#pragma unroll
            for (int ks = 0; ks < 4; ks++)
                ldm4(qa[ks][0], qa[ks][1], qa[ks][2], qa[ks][3],
                     ub + (qa_off + (uint32_t)(ks * 16)) * 2u);
        }
        if (i < 7) {
            load_kv(i + 1);
            cp_commit();
        }

        const uint32_t sk = ub + (uint32_t)(TH * (1 + 2 * (i & 1))) * 2u;
        const uint32_t sv = sk + (uint32_t)TH * 2u;

#pragma unroll
        for (int h2 = 0; h2 < 2; h2++) {
            uint32_t s2[8][2];
#pragma unroll
            for (int j = 0; j < 8; j++) { s2[j][0] = 0u; s2[j][1] = 0u; }
#pragma unroll
            for (int ks = 0; ks < 4; ks++) {
#pragma unroll
                for (int nb = 0; nb < 4; nb++) {
                    uint32_t r0, r1, r2, r3;
                    ldm4(r0, r1, r2, r3,
                         sk + (kb_off + (uint32_t)(((h2 * 4 + nb) * 16) * LDR + ks * 16)) * 2u);
                    uint32_t b01[2] = {r0, r1}, b23[2] = {r2, r3};
                    mma_f16h(s2[2 * nb + 0], qa[ks], b01);
                    mma_f16h(s2[2 * nb + 1], qa[ks], b23);
                }
            }

            const int kvc = i * 128 + h2 * 64 + tig * 2;
#pragma unroll
            for (int j = 0; j < 8; j++) {
                uint32_t pp0 = *(const uint32_t*)(prh0 + kvc + j * 8);
                uint32_t pp1 = *(const uint32_t*)(prh1 + kvc + j * 8);
                s2[j][0] = ex2h2(hadd2u(s2[j][0], pp0));
                s2[j][1] = ex2h2(hadd2u(s2[j][1], pp1));
            }

#pragma unroll
            for (int ks = 0; ks < 4; ks++) {
                uint32_t pa[4] = {s2[2 * ks][0], s2[2 * ks][1],
                                  s2[2 * ks + 1][0], s2[2 * ks + 1][1]};
                mma_f16(lacc, pa, b_ones);
#pragma unroll
                for (int c = 0; c < 4; c++) {
                    uint32_t r0, r1, r2, r3;
                    ldm4t(r0, r1, r2, r3,
                          sv + (vb_off + (uint32_t)(((h2 * 4 + ks) * 16) * LDR + c * 16)) * 2u);
                    uint32_t b01[2] = {r0, r1}, b23[2] = {r2, r3};
                    mma_f16(oacc[2 * c + 0], pa, b01);
                    mma_f16(oacc[2 * c + 1], pa, b23);
                }
            }
        }
    }

    gdc_launch();

    const float inv0 = 1.0f / lacc[0], inv1 = 1.0f / lacc[2];

    const int gr0 = q0 + wid * 16 + gid;
    const size_t o0 = (size_t)b * Nq * Dq + (size_t)gr0 * Dq + h * 64 + tig * 2;
    const size_t o1 = o0 + (size_t)8 * Dq;
#pragma unroll
    for (int t = 0; t < 8; t++) {
        float2 x0 = *(const float2*)(x + o0 + t * 8);
        float2 x1 = *(const float2*)(x + o1 + t * 8);
        float2 w0 = make_float2(oacc[t][0] * inv0 + x0.x, oacc[t][1] * inv0 + x0.y);
        float2 w1 = make_float2(oacc[t][2] * inv1 + x1.x, oacc[t][3] * inv1 + x1.y);
        *(float2*)(s1 + o0 + t * 8) = w0;
        *(float2*)(s1 + o1 + t * 8) = w1;
    }
}

// ---------------------------------------------------------------------------
// fp16 mma.sync GEMM (fp32 accum).  BM=128, BN template (256 or 192), BK=64,
// 4-stage cp.async.  A [M,K] K-major; B [K,N] row-major (ldmatrix.trans).
// 8 warps 2(M)x4(N); warp tile 64 x (BN/4).  PDL as before.
// ---------------------------------------------------------------------------
template <int BN, int EPI, typename CT>
__global__ void __launch_bounds__(256, 1)
mma_gemm(const __half* __restrict__ A, int lda,
         const __half* __restrict__ B, int ldb,
         CT* __restrict__ C, int ldc, int K,
         const float* __restrict__ e0, const float* __restrict__ e1)
{
    constexpr int BM = 128;
    constexpr int BK = 64;
    constexpr int S = 4;
    constexpr int LDRA = 72;
    constexpr int LDRB = BN + 8;
    constexpr int AH = BM * LDRA;
    constexpr int BH = BK * LDRB;
    constexpr int STGH = AH + BH;
    constexpr int MF = 4;
    constexpr int NF = BN / 32;        // n8 frags per warp
    constexpr int NC = NF / 2;         // ldmatrix.x4.trans per k-step
    constexpr int BCPR = BN / 8;       // 16B chunks per B row
    constexpr int BCH = (BK * BCPR) / 256;

    extern __shared__ __half smh[];
    const uint32_t ubase = smem_u32(smh);

    const int tid = threadIdx.x;
    const int lane = tid & 31;
    const int wid = tid >> 5;
    const int wm = wid >> 2, wn = wid & 3;
    const int gid = lane >> 2, tig = lane & 3;

    const int row0 = blockIdx.y * BM;
    const int col0 = blockIdx.x * BN;
    const int niter = K / BK;

    const uint32_t a_off = (uint32_t)((wm * 64 + (lane & 15)) * LDRA + ((lane >> 4) << 3));
    const uint32_t b_off = (uint32_t)(((lane & 7) + (((lane >> 3) & 1) << 3)) * LDRB +
                                      wn * (BN / 4) + ((lane >> 4) << 3));

    auto load_a = [&](int it) {
        const int k0 = it * BK;
        const uint32_t sa = ubase + (uint32_t)((it % S) * STGH) * 2u;
#pragma unroll
        for (int t = 0; t < 4; t++) {
            int id = tid + t * 256;
            int r = id >> 3, j = id & 7;
            cp16(sa + (uint32_t)r * 144u + (uint32_t)j * 16u,
                 A + (size_t)(row0 + r) * lda + k0 + j * 8);
        }
    };
    auto load_b = [&](int it) {
        const int k0 = it * BK;
        const uint32_t sb = ubase + (uint32_t)((it % S) * STGH + AH) * 2u;
#pragma unroll
        for (int t = 0; t < BCH; t++) {
            int id = tid + t * 256;
            int r = id / BCPR, j = id % BCPR;
            cp16(sb + (uint32_t)r * (LDRB * 2) + (uint32_t)j * 16u,
                 B + (size_t)(k0 + r) * ldb + col0 + j * 8);
        }
    };

#pragma unroll
    for (int it = 0; it < S - 1; it++) load_b(it);
    gdc_wait();
#pragma unroll
    for (int it = 0; it < S - 1; it++) {
        load_a(it);
        cp_commit();
    }

    float acc[MF][NF][4];
#pragma unroll
    for (int mf = 0; mf < MF; mf++)
#pragma unroll
        for (int nf = 0; nf < NF; nf++)
#pragma unroll
            for (int q = 0; q < 4; q++) acc[mf][nf][q] = 0.0f;

    for (int i = 0; i < niter; i++) {
        cp_wait<S - 2>();
        __syncthreads();
        if (i + S - 1 < niter) {
            load_b(i + S - 1);
            load_a(i + S - 1);
        }
        cp_commit();

        const uint32_t sa = ubase + (uint32_t)((i % S) * STGH) * 2u;
        const uint32_t sb = ubase + (uint32_t)((i % S) * STGH + AH) * 2u;

#pragma unroll
        for (int ks = 0; ks < BK / 16; ks++) {
            uint32_t a[MF][4], b[NC][4];
#pragma unroll
            for (int mf = 0; mf < MF; mf++)
                ldm4(a[mf][0], a[mf][1], a[mf][2], a[mf][3],
                     sa + (a_off + (uint32_t)(mf * 16 * LDRA + ks * 16)) * 2u);
#pragma unroll
            for (int c = 0; c < NC; c++)
                ldm4t(b[c][0], b[c][1], b[c][2], b[c][3],
                      sb + (b_off + (uint32_t)(ks * 16 * LDRB + c * 16)) * 2u);
#pragma unroll
            for (int mf = 0; mf < MF; mf++)
#pragma unroll
                for (int c = 0; c < NC; c++) {
                    mma_f16(acc[mf][2 * c + 0], a[mf], &b[c][0]);
                    mma_f16(acc[mf][2 * c + 1], a[mf], &b[c][2]);
                }
        }
    }

    gdc_launch();

#pragma unroll
    for (int mf = 0; mf < MF; mf++) {
        const int gr0 = row0 + wm * 64 + mf * 16 + gid;
#pragma unroll
        for (int nf = 0; nf < NF; nf++) {
            const int gc = col0 + wn * (BN / 4) + nf * 8 + tig * 2;
#pragma unroll
            for (int half_ = 0; half_ < 2; half_++) {
                const int gr = gr0 + half_ * 8;
                float v0 = acc[mf][nf][half_ * 2 + 0];
                float v1 = acc[mf][nf][half_ * 2 + 1];
                float o0, o1;
                if constexpr (EPI == EPI_QKV) {
                    o0 = v0 + e0[gc]; o1 = v1 + e0[gc + 1];
                    if (gc < Dq) { o0 *= QSCALE; o1 *= QSCALE; }
                } else if constexpr (EPI == EPI_GELU) {
                    o0 = gelu_fast(v0 + e0[gc]); o1 = gelu_fast(v1 + e0[gc + 1]);
                } else {  // EPI_RES
                    float2 rr = *(const float2*)&e1[(size_t)gr * ldc + gc];
                    o0 = v0 + e0[gc] + rr.x; o1 = v1 + e0[gc + 1] + rr.y;
                }
                if constexpr (sizeof(CT) == 2) {
                    *(__half2*)&C[(size_t)gr * ldc + gc] = __floats2half2_rn(o0, o1);
                } else {
                    *(float2*)&C[(size_t)gr * ldc + gc] = make_float2(o0, o1);
                }
            }
        }
    }
}

// ---------------------------------------------------------------------------
// launch
// ---------------------------------------------------------------------------
extern "C" void kernel_launch(void* const* d_in, const int* in_sizes, int n_in,
                              void* d_out, int out_size)
{
    const float* x     = (const float*)d_in[0];
    const float* prior = (const float*)d_in[1];
    const float* Wqkv  = (const float*)d_in[2];
    const float* bqkv  = (const float*)d_in[3];
    const float* alpha = (const float*)d_in[4];
    const float* ln1_g = (const float*)d_in[5];
    const float* ln1_b = (const float*)d_in[6];
    const float* ln2_g = (const float*)d_in[7];
    const float* ln2_b = (const float*)d_in[8];
    const float* w1    = (const float*)d_in[9];
    const float* b1    = (const float*)d_in[10];
    const float* w2    = (const float*)d_in[11];
    const float* b2    = (const float*)d_in[12];
    float* out = (float*)d_out;

    __half *zp, *qkvp, *h1p, *whqkv, *wh1, *wh2, *pahp;
    float* s1p;
    cudaGetSymbolAddress((void**)&zp, g_z);
    cudaGetSymbolAddress((void**)&qkvp, g_qkv);
    cudaGetSymbolAddress((void**)&s1p, g_s1);
    cudaGetSymbolAddress((void**)&h1p, g_h1);
    cudaGetSymbolAddress((void**)&whqkv, g_whqkv);
    cudaGetSymbolAddress((void**)&wh1, g_wh1);
    cudaGetSymbolAddress((void**)&wh2, g_wh2);
    cudaGetSymbolAddress((void**)&pahp, g_pah);

    const int smem_g   = 4 * (128 * 72 + 64 * 264) * 2;  // BN=256: 208896
    const int smem_qkv = 4 * (128 * 72 + 64 * 200) * 2;  // BN=192: 176128
    const int smem_fa  = 5 * 128 * 72 * 2;               // 92160
    cudaFuncSetAttribute(mma_gemm<192, EPI_QKV, __half>,  cudaFuncAttributeMaxDynamicSharedMemorySize, smem_qkv);
    cudaFuncSetAttribute(mma_gemm<256, EPI_GELU, __half>, cudaFuncAttributeMaxDynamicSharedMemorySize, smem_g);
    cudaFuncSetAttribute(mma_gemm<256, EPI_RES, float>,   cudaFuncAttributeMaxDynamicSharedMemorySize, smem_g);
    cudaFuncSetAttribute(flash_kernel, cudaFuncAttributeMaxDynamicSharedMemorySize, smem_fa);

    const int rows = Bq * Nq;  // 8192

    cudaLaunchAttribute pattr[1];
    pattr[0].id = cudaLaunchAttributeProgrammaticStreamSerialization;
    pattr[0].val.programmaticStreamSerializationAllowed = 1;

    // 0) prep: LN1 (blocks first) + weight/prior casts in one kernel
    prep_kernel<<<LN_BLOCKS + CAST_BLOCKS, 256>>>(
        Wqkv, w1, w2, prior, alpha, x, ln1_g, ln1_b,
        whqkv, wh1, wh2, pahp, zp);

    // 1) qkv = z @ Wqkv + bqkv  (BN=192 for wave fit; q pre-scaled)
    {
        cudaLaunchConfig_t cfg{};
        cfg.gridDim = dim3(3 * Dq / 192, rows / 128); cfg.blockDim = dim3(256);
        cfg.dynamicSmemBytes = smem_qkv; cfg.attrs = pattr; cfg.numAttrs = 1;
        cudaLaunchKernelEx(&cfg, mma_gemm<192, EPI_QKV, __half>,
                           (const __half*)zp, (int)Dq, (const __half*)whqkv, (int)(3 * Dq),
                           (__half*)qkvp, (int)(3 * Dq), (int)Dq, bqkv, (const float*)nullptr);
    }
    // 2) fused attention
    {
        cudaLaunchConfig_t cfg{};
        cfg.gridDim = dim3(Nq / 128, Bq * Hq); cfg.blockDim = dim3(256);
        cfg.dynamicSmemBytes = smem_fa; cfg.attrs = pattr; cfg.numAttrs = 1;
        cudaLaunchKernelEx(&cfg, flash_kernel,
                           (const __half*)qkvp, (const __half*)pahp, x, (float*)s1p);
    }
    // 3) z = LN2(s1)
    {
        cudaLaunchConfig_t cfg{};
        cfg.gridDim = dim3(rows / 8); cfg.blockDim = dim3(256);
        cfg.attrs = pattr; cfg.numAttrs = 1;
        cudaLaunchKernelEx(&cfg, ln_kernel, (const float*)s1p, ln2_g, ln2_b, (__half*)zp);
    }
    // 4) h1 = gelu(z @ w1 + b1)
    {
        cudaLaunchConfig_t cfg{};
        cfg.gridDim = dim3(DFFq / 256, rows / 128); cfg.blockDim = dim3(256);
        cfg.dynamicSmemBytes = smem_g; cfg.attrs = pattr; cfg.numAttrs = 1;
        cudaLaunchKernelEx(&cfg, mma_gemm<256, EPI_GELU, __half>,
                           (const __half*)zp, (int)Dq, (const __half*)wh1, (int)DFFq,
                           (__half*)h1p, (int)DFFq, (int)Dq, b1, (const float*)nullptr);
    }
    // 5) out = s1 + h1 @ w2 + b2
    {
        cudaLaunchConfig_t cfg{};
        cfg.gridDim = dim3(Dq / 256, rows / 128); cfg.blockDim = dim3(256);
        cfg.dynamicSmemBytes = smem_g; cfg.attrs = pattr; cfg.numAttrs = 1;
        cudaLaunchKernelEx(&cfg, mma_gemm<256, EPI_RES, float>,
                           (const __half*)h1p, (int)DFFq, (const __half*)wh2, (int)Dq,
                           out, (int)Dq, (int)DFFq, b2, (const float*)s1p);
    }
}

// round 16
// speedup vs baseline: 1.0582x; 1.0159x over previous
#include <cuda_runtime.h>
#include <cuda_fp16.h>
#include <math.h>
#include <stdint.h>

// ---------------- problem constants ----------------
#define Bq   8
#define Nq   1024
#define Dq   1024
#define Hq   16
#define DFFq 4096
#define FACTORq 0.125f
#define QSCALE 0.18033688f   // 0.125 * log2(e)

// ---------------- scratch (device globals) ----------------
__device__ __half g_z[(size_t)Bq * Nq * Dq];
__device__ __half g_qkv[(size_t)Bq * Nq * 3 * Dq];
__device__ float  g_s1[(size_t)Bq * Nq * Dq];
__device__ __half g_h1[(size_t)Bq * Nq * DFFq];
__device__ __half g_whqkv[(size_t)Dq * 3 * Dq];
__device__ __half g_wh1[(size_t)Dq * DFFq];
__device__ __half g_wh2[(size_t)DFFq * Dq];

#define EPI_QKV    0
#define EPI_GELU   1
#define EPI_RES    2

// ---------------- PTX helpers (sm_90+ generic ISA only) ----------------
__device__ __forceinline__ uint32_t smem_u32(const void* p) {
    uint32_t a;
    asm("{ .reg .u64 t; cvta.to.shared.u64 t, %1; cvt.u32.u64 %0, t; }" : "=r"(a) : "l"(p));
    return a;
}
__device__ __forceinline__ void cp16(uint32_t s, const void* g) {
    asm volatile("cp.async.cg.shared.global [%0], [%1], 16;" :: "r"(s), "l"(g));
}
__device__ __forceinline__ void cp_commit() {
    asm volatile("cp.async.commit_group;" ::: "memory");
}
template <int N>
__device__ __forceinline__ void cp_wait() {
    asm volatile("cp.async.wait_group %0;" :: "n"(N) : "memory");
}
__device__ __forceinline__ void gdc_wait() {
    asm volatile("griddepcontrol.wait;" ::: "memory");
}
__device__ __forceinline__ void gdc_launch() {
    asm volatile("griddepcontrol.launch_dependents;");
}
__device__ __forceinline__ void ldm4(uint32_t& r0, uint32_t& r1, uint32_t& r2, uint32_t& r3,
                                     uint32_t addr) {
    asm volatile("ldmatrix.sync.aligned.m8n8.x4.shared.b16 {%0,%1,%2,%3}, [%4];"
                 : "=r"(r0), "=r"(r1), "=r"(r2), "=r"(r3) : "r"(addr));
}
__device__ __forceinline__ void ldm4t(uint32_t& r0, uint32_t& r1, uint32_t& r2, uint32_t& r3,
                                      uint32_t addr) {
    asm volatile("ldmatrix.sync.aligned.m8n8.x4.trans.shared.b16 {%0,%1,%2,%3}, [%4];"
                 : "=r"(r0), "=r"(r1), "=r"(r2), "=r"(r3) : "r"(addr));
}
__device__ __forceinline__ void mma_f16(float* d, const uint32_t* a, const uint32_t* b) {
    asm volatile(
        "mma.sync.aligned.m16n8k16.row.col.f32.f16.f16.f32 "
        "{%0,%1,%2,%3}, {%4,%5,%6,%7}, {%8,%9}, {%0,%1,%2,%3};"
        : "+f"(d[0]), "+f"(d[1]), "+f"(d[2]), "+f"(d[3])
        : "r"(a[0]), "r"(a[1]), "r"(a[2]), "r"(a[3]), "r"(b[0]), "r"(b[1]));
}
// f16-accumulate variant (output packed like next MMA's A fragments).
__device__ __forceinline__ void mma_f16h(uint32_t* d, const uint32_t* a, const uint32_t* b) {
    asm volatile(
        "mma.sync.aligned.m16n8k16.row.col.f16.f16.f16.f16 "
        "{%0,%1}, {%2,%3,%4,%5}, {%6,%7}, {%0,%1};"
        : "+r"(d[0]), "+r"(d[1])
        : "r"(a[0]), "r"(a[1]), "r"(a[2]), "r"(a[3]), "r"(b[0]), "r"(b[1]));
}
__device__ __forceinline__ uint32_t hadd2u(uint32_t a, uint32_t b) {
    uint32_t r;
    asm("add.rn.f16x2 %0, %1, %2;" : "=r"(r) : "r"(a), "r"(b));
    return r;
}
__device__ __forceinline__ uint32_t ex2h2(uint32_t a) {
    uint32_t r;
    asm("ex2.approx.f16x2 %0, %1;" : "=r"(r) : "r"(a));
    return r;
}
__device__ __forceinline__ float tanh_ap(float x) {
    float r;
    asm("tanh.approx.f32 %0, %1;" : "=f"(r) : "f"(x));
    return r;
}
__device__ __forceinline__ uint32_t packh2(float a, float b) {
    __half2 h = __floats2half2_rn(a, b);
    return *(uint32_t*)&h;
}
__device__ __forceinline__ float gelu_fast(float x) {
    float x3 = x * x * x;
    return 0.5f * x * (1.0f + tanh_ap(0.7978845608028654f * (x + 0.044715f * x3)));
}

// ---------------------------------------------------------------------------
// Prep kernel: LN1 blocks FIRST, then weight casts (NO prior processing).
// ---------------------------------------------------------------------------
#define SEG0 786432
#define SEG1 (SEG0 + 1048576)
#define SEG2 (SEG1 + 1048576)
#define LN_BLOCKS (Bq * Nq / 8)       // 1024
#define CAST_BLOCKS (SEG2 / 256)      // 11264
__global__ void __launch_bounds__(256)
prep_kernel(const float* __restrict__ wqkv, const float* __restrict__ w1,
            const float* __restrict__ w2,
            const float* __restrict__ x, const float* __restrict__ ln_g,
            const float* __restrict__ ln_b,
            __half* __restrict__ hq, __half* __restrict__ h1,
            __half* __restrict__ h2,
            __half* __restrict__ z)
{
    if (blockIdx.x >= LN_BLOCKS) {
        const int i = (blockIdx.x - LN_BLOCKS) * 256 + threadIdx.x;
        const float* src;
        __half* dst;
        int li;
        if (i < SEG0)      { src = wqkv;  dst = hq; li = i; }
        else if (i < SEG1) { src = w1;    dst = h1; li = i - SEG0; }
        else               { src = w2;    dst = h2; li = i - SEG1; }
        float4 v = ((const float4*)src)[li];
        uint2 u;
        u.x = packh2(v.x, v.y);
        u.y = packh2(v.z, v.w);
        ((uint2*)dst)[li] = u;
        return;
    }
    // ---- LN1 segment (scheduled first) ----
    const int warp = threadIdx.x >> 5, lane = threadIdx.x & 31;
    const int row = blockIdx.x * 8 + warp;
    const float4* xr = (const float4*)(x + (size_t)row * Dq);

    float4 v[8];
    float s = 0.0f, s2 = 0.0f;
#pragma unroll
    for (int t = 0; t < 8; t++) {
        v[t] = xr[lane + t * 32];
        s += v[t].x + v[t].y + v[t].z + v[t].w;
        s2 += v[t].x * v[t].x + v[t].y * v[t].y + v[t].z * v[t].z + v[t].w * v[t].w;
    }
#pragma unroll
    for (int o = 16; o; o >>= 1) {
        s += __shfl_xor_sync(0xffffffffu, s, o);
        s2 += __shfl_xor_sync(0xffffffffu, s2, o);
    }
    const float mu = s * (1.0f / Dq);
    const float var = s2 * (1.0f / Dq) - mu * mu;
    const float inv = rsqrtf(var + 1e-5f);

    __half* orow = z + (size_t)row * Dq;
#pragma unroll
    for (int t = 0; t < 8; t++) {
        const int i = (lane + t * 32) * 4;
        float4 gg = *(const float4*)&ln_g[i];
        float4 bv = *(const float4*)&ln_b[i];
        uint2 u;
        u.x = packh2((v[t].x - mu) * inv * gg.x + bv.x, (v[t].y - mu) * inv * gg.y + bv.y);
        u.y = packh2((v[t].z - mu) * inv * gg.z + bv.z, (v[t].w - mu) * inv * gg.w + bv.w);
        *(uint2*)&orow[i] = u;
    }
}

// ---------------------------------------------------------------------------
// LayerNorm, warp-per-row (LN2).
// ---------------------------------------------------------------------------
__global__ void __launch_bounds__(256)
ln_kernel(const float* __restrict__ x, const float* __restrict__ g,
          const float* __restrict__ bb, __half* __restrict__ out)
{
    gdc_launch();
    gdc_wait();
    const int warp = threadIdx.x >> 5, lane = threadIdx.x & 31;
    const int row = blockIdx.x * 8 + warp;
    const float4* xr = (const float4*)(x + (size_t)row * Dq);

    float4 v[8];
    float s = 0.0f, s2 = 0.0f;
#pragma unroll
    for (int t = 0; t < 8; t++) {
        v[t] = xr[lane + t * 32];
        s += v[t].x + v[t].y + v[t].z + v[t].w;
        s2 += v[t].x * v[t].x + v[t].y * v[t].y + v[t].z * v[t].z + v[t].w * v[t].w;
    }
#pragma unroll
    for (int o = 16; o; o >>= 1) {
        s += __shfl_xor_sync(0xffffffffu, s, o);
        s2 += __shfl_xor_sync(0xffffffffu, s2, o);
    }
    const float mu = s * (1.0f / Dq);
    const float var = s2 * (1.0f / Dq) - mu * mu;
    const float inv = rsqrtf(var + 1e-5f);

    __half* orow = out + (size_t)row * Dq;
#pragma unroll
    for (int t = 0; t < 8; t++) {
        const int i = (lane + t * 32) * 4;
        float4 gg = *(const float4*)&g[i];
        float4 bv = *(const float4*)&bb[i];
        uint2 u;
        u.x = packh2((v[t].x - mu) * inv * gg.x + bv.x, (v[t].y - mu) * inv * gg.y + bv.y);
        u.y = packh2((v[t].z - mu) * inv * gg.z + bv.z, (v[t].w - mu) * inv * gg.w + bv.w);
        *(uint2*)&orow[i] = u;
    }
}

// ---------------------------------------------------------------------------
// Flash attention (R11 config; fp32 prior scaled in registers).
// half2 softmax, 2 CTAs/SM, 8 warps x 16 q-rows, kv tile in two nb-halves.
// grid = (N/128, B*H), 256 threads.
// ---------------------------------------------------------------------------
__global__ void __launch_bounds__(256, 2)
flash_kernel(const __half* __restrict__ qkv,
             const float* __restrict__ prior,
             const float* __restrict__ alpha_p,
             const float* __restrict__ x,
             float* __restrict__ s1)
{
    constexpr int LDR = 72;
    constexpr int TH = 128 * LDR;
    extern __shared__ __half sm[];
    const uint32_t ub = smem_u32(sm);

    const int tid = threadIdx.x;
    const int lane = tid & 31;
    const int wid = tid >> 5;
    const int gid = lane >> 2, tig = lane & 3;

    const int qt = blockIdx.x;
    const int bh = blockIdx.y;
    const int b = bh >> 4, h = bh & 15;
    const int q0 = qt * 128;

    const __half* qbase = qkv + (size_t)b * Nq * (3 * Dq) + (size_t)h * 64;
    const __half* kbase = qbase + Dq;
    const __half* vbase = qbase + 2 * Dq;

    gdc_wait();
    const float af = alpha_p[0] * QSCALE;

    auto load_q = [&]() {
#pragma unroll
        for (int t = 0; t < 4; t++) {
            int id = tid + t * 256;
            int r = id >> 3, j = id & 7;
            cp16(ub + (uint32_t)(r * LDR + j * 8) * 2u,
                 qbase + (size_t)(q0 + r) * (3 * Dq) + j * 8);
        }
    };
    auto load_kv = [&](int i) {
        const int kv0 = i * 128;
        const uint32_t sk = ub + (uint32_t)(TH * (1 + 2 * (i & 1))) * 2u;
        const uint32_t sv = sk + (uint32_t)TH * 2u;
#pragma unroll
        for (int t = 0; t < 4; t++) {
            int id = tid + t * 256;
            int r = id >> 3, j = id & 7;
            cp16(sk + (uint32_t)(r * LDR + j * 8) * 2u,
                 kbase + (size_t)(kv0 + r) * (3 * Dq) + j * 8);
        }
#pragma unroll
        for (int t = 0; t < 4; t++) {
            int id = tid + t * 256;
            int r = id >> 3, j = id & 7;
            cp16(sv + (uint32_t)(r * LDR + j * 8) * 2u,
                 vbase + (size_t)(kv0 + r) * (3 * Dq) + j * 8);
        }
    };

    load_q();
    load_kv(0);
    cp_commit();

    const uint32_t qa_off = (uint32_t)((wid * 16 + (lane & 15)) * LDR + ((lane >> 4) << 3));
    const uint32_t kb_off = (uint32_t)(((lane & 7) + ((lane >> 4) << 3)) * LDR +
                                       (((lane >> 3) & 1) << 3));
    const uint32_t vb_off = (uint32_t)(((lane & 7) + (((lane >> 3) & 1) << 3)) * LDR +
                                       ((lane >> 4) << 3));

    uint32_t qa[4][4];
    float oacc[8][4];
#pragma unroll
    for (int t = 0; t < 8; t++)
#pragma unroll
        for (int q = 0; q < 4; q++) oacc[t][q] = 0.0f;
    float lacc[4] = {0.0f, 0.0f, 0.0f, 0.0f};
    const uint32_t ONES = 0x3C003C00u;
    const uint32_t b_ones[2] = {ONES, ONES};

    const float* pr0 = prior + (size_t)b * Nq * Nq + (size_t)(q0 + wid * 16 + gid) * Nq;
    const float* pr1 = pr0 + 8 * Nq;

    for (int i = 0; i < 8; i++) {
        cp_wait<0>();
        __syncthreads();
        if (i == 0) {
#pragma unroll
            for (int ks = 0; ks < 4; ks++)
                ldm4(qa[ks][0], qa[ks][1], qa[ks][2], qa[ks][3],
                     ub + (qa_off + (uint32_t)(ks * 16)) * 2u);
        }
        if (i < 7) {
            load_kv(i + 1);
            cp_commit();
        }

        const uint32_t sk = ub + (uint32_t)(TH * (1 + 2 * (i & 1))) * 2u;
        const uint32_t sv = sk + (uint32_t)TH * 2u;

#pragma unroll
        for (int h2 = 0; h2 < 2; h2++) {
            uint32_t s2[8][2];
#pragma unroll
            for (int j = 0; j < 8; j++) { s2[j][0] = 0u; s2[j][1] = 0u; }
#pragma unroll
            for (int ks = 0; ks < 4; ks++) {
#pragma unroll
                for (int nb = 0; nb < 4; nb++) {
                    uint32_t r0, r1, r2, r3;
                    ldm4(r0, r1, r2, r3,
                         sk + (kb_off + (uint32_t)(((h2 * 4 + nb) * 16) * LDR + ks * 16)) * 2u);
                    uint32_t b01[2] = {r0, r1}, b23[2] = {r2, r3};
                    mma_f16h(s2[2 * nb + 0], qa[ks], b01);
                    mma_f16h(s2[2 * nb + 1], qa[ks], b23);
                }
            }

            const int kvc = i * 128 + h2 * 64 + tig * 2;
#pragma unroll
            for (int j = 0; j < 8; j++) {
                float2 f0 = *(const float2*)(pr0 + kvc + j * 8);
                float2 f1 = *(const float2*)(pr1 + kvc + j * 8);
                uint32_t pp0 = packh2(af * f0.x, af * f0.y);
                uint32_t pp1 = packh2(af * f1.x, af * f1.y);
                s2[j][0] = ex2h2(hadd2u(s2[j][0], pp0));
                s2[j][1] = ex2h2(hadd2u(s2[j][1], pp1));
            }

#pragma unroll
            for (int ks = 0; ks < 4; ks++) {
                uint32_t pa[4] = {s2[2 * ks][0], s2[2 * ks][1],
                                  s2[2 * ks + 1][0], s2[2 * ks + 1][1]};
                mma_f16(lacc, pa, b_ones);
#pragma unroll
                for (int c = 0; c < 4; c++) {
                    uint32_t r0, r1, r2, r3;
                    ldm4t(r0, r1, r2, r3,
                          sv + (vb_off + (uint32_t)(((h2 * 4 + ks) * 16) * LDR + c * 16)) * 2u);
                    uint32_t b01[2] = {r0, r1}, b23[2] = {r2, r3};
                    mma_f16(oacc[2 * c + 0], pa, b01);
                    mma_f16(oacc[2 * c + 1], pa, b23);
                }
            }
        }
    }

    gdc_launch();

    const float inv0 = 1.0f / lacc[0], inv1 = 1.0f / lacc[2];

    const int gr0 = q0 + wid * 16 + gid;
    const size_t o0 = (size_t)b * Nq * Dq + (size_t)gr0 * Dq + h * 64 + tig * 2;
    const size_t o1 = o0 + (size_t)8 * Dq;
#pragma unroll
    for (int t = 0; t < 8; t++) {
        float2 x0 = *(const float2*)(x + o0 + t * 8);
        float2 x1 = *(const float2*)(x + o1 + t * 8);
        float2 w0 = make_float2(oacc[t][0] * inv0 + x0.x, oacc[t][1] * inv0 + x0.y);
        float2 w1 = make_float2(oacc[t][2] * inv1 + x1.x, oacc[t][3] * inv1 + x1.y);
        *(float2*)(s1 + o0 + t * 8) = w0;
        *(float2*)(s1 + o1 + t * 8) = w1;
    }
}

// ---------------------------------------------------------------------------
// fp16 mma.sync GEMM (fp32 accum).  BM=128, BN template, BK=64, 4-stage
// cp.async.  A [M,K] K-major; B [K,N] row-major (ldmatrix.trans fragments).
// 8 warps 2(M)x4(N); warp tile 64 x (BN/4).  PDL as before.
// ---------------------------------------------------------------------------
template <int BN, int EPI, typename CT>
__global__ void __launch_bounds__(256, 1)
mma_gemm(const __half* __restrict__ A, int lda,
         const __half* __restrict__ B, int ldb,
         CT* __restrict__ C, int ldc, int K,
         const float* __restrict__ e0, const float* __restrict__ e1)
{
    constexpr int BM = 128;
    constexpr int BK = 64;
    constexpr int S = 4;
    constexpr int LDRA = 72;
    constexpr int LDRB = BN + 8;
    constexpr int AH = BM * LDRA;
    constexpr int BH = BK * LDRB;
    constexpr int STGH = AH + BH;
    constexpr int MF = 4;
    constexpr int NF = BN / 32;
    constexpr int NC = NF / 2;
    constexpr int BCPR = BN / 8;
    constexpr int BCH = (BK * BCPR) / 256;

    extern __shared__ __half smh[];
    const uint32_t ubase = smem_u32(smh);

    const int tid = threadIdx.x;
    const int lane = tid & 31;
    const int wid = tid >> 5;
    const int wm = wid >> 2, wn = wid & 3;
    const int gid = lane >> 2, tig = lane & 3;

    const int row0 = blockIdx.y * BM;
    const int col0 = blockIdx.x * BN;
    const int niter = K / BK;

    const uint32_t a_off = (uint32_t)((wm * 64 + (lane & 15)) * LDRA + ((lane >> 4) << 3));
    const uint32_t b_off = (uint32_t)(((lane & 7) + (((lane >> 3) & 1) << 3)) * LDRB +
                                      wn * (BN / 4) + ((lane >> 4) << 3));

    auto load_a = [&](int it) {
        const int k0 = it * BK;
        const uint32_t sa = ubase + (uint32_t)((it % S) * STGH) * 2u;
#pragma unroll
        for (int t = 0; t < 4; t++) {
            int id = tid + t * 256;
            int r = id >> 3, j = id & 7;
            cp16(sa + (uint32_t)r * 144u + (uint32_t)j * 16u,
                 A + (size_t)(row0 + r) * lda + k0 + j * 8);
        }
    };
    auto load_b = [&](int it) {
        const int k0 = it * BK;
        const uint32_t sb = ubase + (uint32_t)((it % S) * STGH + AH) * 2u;
#pragma unroll
        for (int t = 0; t < BCH; t++) {
            int id = tid + t * 256;
            int r = id / BCPR, j = id % BCPR;
            cp16(sb + (uint32_t)r * (LDRB * 2) + (uint32_t)j * 16u,
                 B + (size_t)(k0 + r) * ldb + col0 + j * 8);
        }
    };

#pragma unroll
    for (int it = 0; it < S - 1; it++) load_b(it);
    gdc_wait();
#pragma unroll
    for (int it = 0; it < S - 1; it++) {
        load_a(it);
        cp_commit();
    }

    float acc[MF][NF][4];
#pragma unroll
    for (int mf = 0; mf < MF; mf++)
#pragma unroll
        for (int nf = 0; nf < NF; nf++)
#pragma unroll
            for (int q = 0; q < 4; q++) acc[mf][nf][q] = 0.0f;

    for (int i = 0; i < niter; i++) {
        cp_wait<S - 2>();
        __syncthreads();
        if (i + S - 1 < niter) {
            load_b(i + S - 1);
            load_a(i + S - 1);
        }
        cp_commit();

        const uint32_t sa = ubase + (uint32_t)((i % S) * STGH) * 2u;
        const uint32_t sb = ubase + (uint32_t)((i % S) * STGH + AH) * 2u;

#pragma unroll
        for (int ks = 0; ks < BK / 16; ks++) {
            uint32_t a[MF][4], b[NC][4];
#pragma unroll
            for (int mf = 0; mf < MF; mf++)
                ldm4(a[mf][0], a[mf][1], a[mf][2], a[mf][3],
                     sa + (a_off + (uint32_t)(mf * 16 * LDRA + ks * 16)) * 2u);
#pragma unroll
            for (int c = 0; c < NC; c++)
                ldm4t(b[c][0], b[c][1], b[c][2], b[c][3],
                      sb + (b_off + (uint32_t)(ks * 16 * LDRB + c * 16)) * 2u);
#pragma unroll
            for (int mf = 0; mf < MF; mf++)
#pragma unroll
                for (int c = 0; c < NC; c++) {
                    mma_f16(acc[mf][2 * c + 0], a[mf], &b[c][0]);
                    mma_f16(acc[mf][2 * c + 1], a[mf], &b[c][2]);
                }
        }
    }

    gdc_launch();

#pragma unroll
    for (int mf = 0; mf < MF; mf++) {
        const int gr0 = row0 + wm * 64 + mf * 16 + gid;
#pragma unroll
        for (int nf = 0; nf < NF; nf++) {
            const int gc = col0 + wn * (BN / 4) + nf * 8 + tig * 2;
#pragma unroll
            for (int half_ = 0; half_ < 2; half_++) {
                const int gr = gr0 + half_ * 8;
                float v0 = acc[mf][nf][half_ * 2 + 0];
                float v1 = acc[mf][nf][half_ * 2 + 1];
                float o0, o1;
                if constexpr (EPI == EPI_QKV) {
                    o0 = v0 + e0[gc]; o1 = v1 + e0[gc + 1];
                    if (gc < Dq) { o0 *= QSCALE; o1 *= QSCALE; }
                } else if constexpr (EPI == EPI_GELU) {
                    o0 = gelu_fast(v0 + e0[gc]); o1 = gelu_fast(v1 + e0[gc + 1]);
                } else {  // EPI_RES
                    float2 rr = *(const float2*)&e1[(size_t)gr * ldc + gc];
                    o0 = v0 + e0[gc] + rr.x; o1 = v1 + e0[gc + 1] + rr.y;
                }
                if constexpr (sizeof(CT) == 2) {
                    *(__half2*)&C[(size_t)gr * ldc + gc] = __floats2half2_rn(o0, o1);
                } else {
                    *(float2*)&C[(size_t)gr * ldc + gc] = make_float2(o0, o1);
                }
            }
        }
    }
}

// ---------------------------------------------------------------------------
// launch
// ---------------------------------------------------------------------------
extern "C" void kernel_launch(void* const* d_in, const int* in_sizes, int n_in,
                              void* d_out, int out_size)
{
    const float* x     = (const float*)d_in[0];
    const float* prior = (const float*)d_in[1];
    const float* Wqkv  = (const float*)d_in[2];
    const float* bqkv  = (const float*)d_in[3];
    const float* alpha = (const float*)d_in[4];
    const float* ln1_g = (const float*)d_in[5];
    const float* ln1_b = (const float*)d_in[6];
    const float* ln2_g = (const float*)d_in[7];
    const float* ln2_b = (const float*)d_in[8];
    const float* w1    = (const float*)d_in[9];
    const float* b1    = (const float*)d_in[10];
    const float* w2    = (const float*)d_in[11];
    const float* b2    = (const float*)d_in[12];
    float* out = (float*)d_out;

    __half *zp, *qkvp, *h1p, *whqkv, *wh1, *wh2;
    float* s1p;
    cudaGetSymbolAddress((void**)&zp, g_z);
    cudaGetSymbolAddress((void**)&qkvp, g_qkv);
    cudaGetSymbolAddress((void**)&s1p, g_s1);
    cudaGetSymbolAddress((void**)&h1p, g_h1);
    cudaGetSymbolAddress((void**)&whqkv, g_whqkv);
    cudaGetSymbolAddress((void**)&wh1, g_wh1);
    cudaGetSymbolAddress((void**)&wh2, g_wh2);

    const int smem_g   = 4 * (128 * 72 + 64 * 264) * 2;  // BN=256: 208896
    const int smem_qkv = 4 * (128 * 72 + 64 * 200) * 2;  // BN=192: 176128
    const int smem_fa  = 5 * 128 * 72 * 2;               // 92160
    cudaFuncSetAttribute(mma_gemm<192, EPI_QKV, __half>,  cudaFuncAttributeMaxDynamicSharedMemorySize, smem_qkv);
    cudaFuncSetAttribute(mma_gemm<256, EPI_GELU, __half>, cudaFuncAttributeMaxDynamicSharedMemorySize, smem_g);
    cudaFuncSetAttribute(mma_gemm<256, EPI_RES, float>,   cudaFuncAttributeMaxDynamicSharedMemorySize, smem_g);
    cudaFuncSetAttribute(flash_kernel, cudaFuncAttributeMaxDynamicSharedMemorySize, smem_fa);

    const int rows = Bq * Nq;  // 8192

    cudaLaunchAttribute pattr[1];
    pattr[0].id = cudaLaunchAttributeProgrammaticStreamSerialization;
    pattr[0].val.programmaticStreamSerializationAllowed = 1;

    // 0) prep: LN1 (blocks first) + weight casts (no prior processing)
    prep_kernel<<<LN_BLOCKS + CAST_BLOCKS, 256>>>(
        Wqkv, w1, w2, x, ln1_g, ln1_b, whqkv, wh1, wh2, zp);

    // 1) qkv = z @ Wqkv + bqkv  (BN=192; q pre-scaled by F*log2e)
    {
        cudaLaunchConfig_t cfg{};
        cfg.gridDim = dim3(3 * Dq / 192, rows / 128); cfg.blockDim = dim3(256);
        cfg.dynamicSmemBytes = smem_qkv; cfg.attrs = pattr; cfg.numAttrs = 1;
        cudaLaunchKernelEx(&cfg, mma_gemm<192, EPI_QKV, __half>,
                           (const __half*)zp, (int)Dq, (const __half*)whqkv, (int)(3 * Dq),
                           (__half*)qkvp, (int)(3 * Dq), (int)Dq, bqkv, (const float*)nullptr);
    }
    // 2) fused attention (fp32 prior)
    {
        cudaLaunchConfig_t cfg{};
        cfg.gridDim = dim3(Nq / 128, Bq * Hq); cfg.blockDim = dim3(256);
        cfg.dynamicSmemBytes = smem_fa; cfg.attrs = pattr; cfg.numAttrs = 1;
        cudaLaunchKernelEx(&cfg, flash_kernel,
                           (const __half*)qkvp, prior, alpha, x, (float*)s1p);
    }
    // 3) z = LN2(s1)
    {
        cudaLaunchConfig_t cfg{};
        cfg.gridDim = dim3(rows / 8); cfg.blockDim = dim3(256);
        cfg.attrs = pattr; cfg.numAttrs = 1;
        cudaLaunchKernelEx(&cfg, ln_kernel, (const float*)s1p, ln2_g, ln2_b, (__half*)zp);
    }
    // 4) h1 = gelu(z @ w1 + b1)
    {
        cudaLaunchConfig_t cfg{};
        cfg.gridDim = dim3(DFFq / 256, rows / 128); cfg.blockDim = dim3(256);
        cfg.dynamicSmemBytes = smem_g; cfg.attrs = pattr; cfg.numAttrs = 1;
        cudaLaunchKernelEx(&cfg, mma_gemm<256, EPI_GELU, __half>,
                           (const __half*)zp, (int)Dq, (const __half*)wh1, (int)DFFq,
                           (__half*)h1p, (int)DFFq, (int)Dq, b1, (const float*)nullptr);
    }
    // 5) out = s1 + h1 @ w2 + b2
    {
        cudaLaunchConfig_t cfg{};
        cfg.gridDim = dim3(Dq / 256, rows / 128); cfg.blockDim = dim3(256);
        cfg.dynamicSmemBytes = smem_g; cfg.attrs = pattr; cfg.numAttrs = 1;
        cudaLaunchKernelEx(&cfg, mma_gemm<256, EPI_RES, float>,
                           (const __half*)h1p, (int)DFFq, (const __half*)wh2, (int)Dq,
                           out, (int)Dq, (int)DFFq, b2, (const float*)s1p);
    }
}